// round 13
// baseline (speedup 1.0000x reference)
#include <cuda_runtime.h>
#include <cuda_bf16.h>
#include <math.h>
#include <stdint.h>

#define Bsz  4
#define Tlen 512
#define Edim 1024
#define Vdim 32000
#define GDIM (4*Edim)           // 4096
#define MROWS (Tlen*Bsz)        // 2048
#define NBLK 128
#define LOGB (-1.0005003335835335e-3)

// hybrid projection split: 167 mma col-tiles (128 wide) + 166 ffma stripes (64 wide)
#define HB_CM 167
#define HB_N0 (128*HB_CM)       // 21376
#define HB_NF 166               // ffma stripes

// ---------------- scratch ----------------
static __device__ __align__(16) __nv_bfloat16 g_xbf [MROWS * Edim];
static __device__ __align__(16) float g_gates[MROWS * GDIM];
static __device__ __align__(16) __nv_bfloat16 g_h0bf[(Tlen+1) * Bsz*Edim];
static __device__ __align__(16) __nv_bfloat16 g_h1bf[(Tlen+1) * Bsz*Edim];
static __device__ __align__(16) __nv_bfloat16 g_wih0bf[GDIM * Edim];
static __device__ __align__(16) __nv_bfloat16 g_wih1bf[GDIM * Edim];
static __device__ __align__(16) __nv_bfloat16 g_wprojbf[(size_t)Vdim * Edim];

// grid-barrier (proven)
static __device__ unsigned int g_arrive;
static __device__ unsigned int g_release;
__global__ void bar_reset() { g_arrive = 0; g_release = 0; }

// ---------------- helpers ----------------
__device__ __forceinline__ float tanh_acc(float x) {
    float ax = fabsf(x);
    float t  = expf(-2.f * ax);
    float r  = (1.f - t) / (1.f + t);
    return copysignf(r, x);
}
__device__ __forceinline__ float sigm(float x) { return 1.f / (1.f + expf(-x)); }

__device__ __forceinline__ void grid_barrier_t0(unsigned int gen) {
    __threadfence();
    unsigned int prev = atomicAdd(&g_arrive, 1u);
    if (prev + 1u == gen * NBLK) {
        __threadfence();
        asm volatile("st.release.gpu.u32 [%0], %1;"
                     :: "l"(&g_release), "r"(gen) : "memory");
    } else {
        unsigned int v;
        do {
            asm volatile("ld.acquire.gpu.u32 %0, [%1];"
                         : "=r"(v) : "l"(&g_release) : "memory");
        } while (v < gen);
    }
}

__device__ __forceinline__ void fma2(unsigned long long& acc,
                                     unsigned long long a, unsigned long long b) {
    asm("fma.rn.f32x2 %0, %1, %2, %0;" : "+l"(acc) : "l"(a), "l"(b));
}
__device__ __forceinline__ float f2sum(unsigned long long acc) {
    uint32_t lo, hi;
    asm("mov.b64 {%0,%1}, %2;" : "=r"(lo), "=r"(hi) : "l"(acc));
    return __uint_as_float(lo) + __uint_as_float(hi);
}
__device__ __forceinline__ unsigned long long packf2(float a, float b) {
    unsigned long long r;
    asm("mov.b64 %0, {%1,%2};" : "=l"(r) : "f"(a), "f"(b));
    return r;
}
__device__ __forceinline__ uint32_t packbf(float a, float b) {
    __nv_bfloat162 t = __floats2bfloat162_rn(a, b);
    return *(uint32_t*)&t;
}

__device__ __forceinline__ void ldsm_x4(uint32_t& r0, uint32_t& r1, uint32_t& r2, uint32_t& r3,
                                        uint32_t addr) {
    asm volatile("ldmatrix.sync.aligned.m8n8.x4.shared.b16 {%0,%1,%2,%3}, [%4];"
                 : "=r"(r0), "=r"(r1), "=r"(r2), "=r"(r3) : "r"(addr));
}
__device__ __forceinline__ void mma_bf16(float c[4], const uint32_t a[4], const uint32_t b[2]) {
    asm volatile(
        "mma.sync.aligned.m16n8k16.row.col.f32.bf16.bf16.f32 "
        "{%0,%1,%2,%3}, {%4,%5,%6,%7}, {%8,%9}, {%0,%1,%2,%3};"
        : "+f"(c[0]), "+f"(c[1]), "+f"(c[2]), "+f"(c[3])
        : "r"(a[0]), "r"(a[1]), "r"(a[2]), "r"(a[3]), "r"(b[0]), "r"(b[1]));
}

// ---------------- fp32 -> bf16 ----------------
__global__ void f2bf_kernel(const float* __restrict__ s, __nv_bfloat16* __restrict__ d, int n) {
    int idx = (blockIdx.x * blockDim.x + threadIdx.x) * 4;
    if (idx >= n) return;
    float4 v = *(const float4*)(s + idx);
    uint2 p;
    p.x = packbf(v.x, v.y); p.y = packbf(v.z, v.w);
    *(uint2*)(d + idx) = p;
}

// ---------------- embedding ----------------
__global__ void embed_kernel(const int* __restrict__ tokens, const float* __restrict__ emb) {
    int id = blockIdx.x * blockDim.x + threadIdx.x;
    const int EV = Edim / 4;
    if (id >= MROWS * EV) return;
    int e4 = id % EV;
    int m  = id / EV;
    int b  = m & 3, t = m >> 2;
    int tok = tokens[b * Tlen + t];
    float4 v = ((const float4*)(emb + (size_t)tok * Edim))[e4];
    uint2 p; p.x = packbf(v.x, v.y); p.y = packbf(v.z, v.w);
    *(uint2*)(g_xbf + (size_t)id * 4) = p;
}

// ---------------- bf16 tensor-core GEMM (NT) — round-8 proven (gates) ----------------
__global__ __launch_bounds__(256)
void gemm_bf16_nt(const __nv_bfloat16* __restrict__ A, const __nv_bfloat16* __restrict__ B,
                  float* __restrict__ C, int M, int N, int K,
                  const float* __restrict__ bias1, const float* __restrict__ bias2,
                  int remap)
{
    __shared__ __align__(16) __nv_bfloat16 As[128 * 40];
    __shared__ __align__(16) __nv_bfloat16 Bs[128 * 40];
    const int tid  = threadIdx.x;
    const int wid  = tid >> 5, lane = tid & 31;
    const int g    = lane >> 2, tig = lane & 3;
    const int q    = lane >> 3, r = lane & 7;
    const int warp_m = (wid >> 2) * 64;
    const int warp_n = (wid & 3) * 32;
    const int row0 = blockIdx.x * 128;
    const int col0 = blockIdx.y * 128;

    const int ldr = tid >> 2;
    const int ldc = (tid & 3) * 8;

    const __nv_bfloat16* Ap0 = A + (size_t)(row0 + ldr) * K + ldc;
    const __nv_bfloat16* Ap1 = A + (size_t)(row0 + ldr + 64) * K + ldc;
    const __nv_bfloat16* Bp0 = B + (size_t)(col0 + ldr) * K + ldc;
    const __nv_bfloat16* Bp1 = B + (size_t)(col0 + ldr + 64) * K + ldc;

    const uint32_t as_base = (uint32_t)__cvta_generic_to_shared(As);
    const uint32_t bs_base = (uint32_t)__cvta_generic_to_shared(Bs);
    const uint32_t a_addr0 = as_base + (uint32_t)(((warp_m + (q & 1) * 8 + r) * 40 + (q >> 1) * 8) * 2);
    const uint32_t b_addr0 = bs_base + (uint32_t)(((warp_n + (q & 1) * 8 + r) * 40 + (q >> 1) * 8) * 2);

    float acc[16][4];
#pragma unroll
    for (int i = 0; i < 16; i++)
#pragma unroll
        for (int j = 0; j < 4; j++) acc[i][j] = 0.f;

    uint4 pa0 = *(const uint4*)Ap0;
    uint4 pa1 = *(const uint4*)Ap1;
    uint4 pb0 = *(const uint4*)Bp0;
    uint4 pb1 = *(const uint4*)Bp1;

    for (int kb = 0; kb < K; kb += 32) {
        *(uint4*)&As[ldr * 40 + ldc]        = pa0;
        *(uint4*)&As[(ldr + 64) * 40 + ldc] = pa1;
        *(uint4*)&Bs[ldr * 40 + ldc]        = pb0;
        *(uint4*)&Bs[(ldr + 64) * 40 + ldc] = pb1;
        __syncthreads();

        if (kb + 32 < K) {
            pa0 = *(const uint4*)(Ap0 + kb + 32);
            pa1 = *(const uint4*)(Ap1 + kb + 32);
            pb0 = *(const uint4*)(Bp0 + kb + 32);
            pb1 = *(const uint4*)(Bp1 + kb + 32);
        }

#pragma unroll
        for (int ks = 0; ks < 2; ks++) {
            uint32_t af[4][4], bf[4][2];
#pragma unroll
            for (int mt = 0; mt < 4; mt++)
                ldsm_x4(af[mt][0], af[mt][1], af[mt][2], af[mt][3],
                        a_addr0 + (uint32_t)((mt * 16 * 40 + ks * 16) * 2));
#pragma unroll
            for (int bt = 0; bt < 2; bt++) {
                uint32_t m0, m1, m2, m3;
                ldsm_x4(m0, m1, m2, m3,
                        b_addr0 + (uint32_t)((bt * 16 * 40 + ks * 16) * 2));
                bf[bt * 2 + 0][0] = m0; bf[bt * 2 + 1][0] = m1;
                bf[bt * 2 + 0][1] = m2; bf[bt * 2 + 1][1] = m3;
            }
#pragma unroll
            for (int mt = 0; mt < 4; mt++)
#pragma unroll
                for (int nt = 0; nt < 4; nt++)
                    mma_bf16(acc[mt * 4 + nt], af[mt], bf[nt]);
        }
        __syncthreads();
    }

#pragma unroll
    for (int mt = 0; mt < 4; mt++) {
        int m0 = row0 + warp_m + mt * 16 + g;
        int m1 = m0 + 8;
        int r0 = remap ? ((m0 & 3) * Tlen + (m0 >> 2)) : m0;
        int r1 = remap ? ((m1 & 3) * Tlen + (m1 >> 2)) : m1;
#pragma unroll
        for (int nt = 0; nt < 4; nt++) {
            int n = col0 + warp_n + nt * 8 + tig * 2;
            float bv0 = 0.f, bv1 = 0.f;
            if (bias1) { bv0 += bias1[n]; bv1 += bias1[n + 1]; }
            if (bias2) { bv0 += bias2[n]; bv1 += bias2[n + 1]; }
            float* c = acc[mt * 4 + nt];
            *(float2*)&C[(size_t)r0 * N + n] = make_float2(c[0] + bv0, c[1] + bv1);
            *(float2*)&C[(size_t)r1 * N + n] = make_float2(c[2] + bv0, c[3] + bv1);
        }
    }
}

// ---------------- hybrid projection GEMM: 8 mma warps (128x128 tile) +
// 4 ffma warps (128x64 stripe) in one block; both pipes busy ----------------
__global__ __launch_bounds__(384, 1)
void gemm_hybrid(const __nv_bfloat16* __restrict__ A, const __nv_bfloat16* __restrict__ B,
                 float* __restrict__ C, int M, int N, int K)
{
    __shared__ __align__(16) __nv_bfloat16 As[128 * 40];   // 10240 B
    __shared__ __align__(16) __nv_bfloat16 Bs[128 * 40];   // 10240 B
    __shared__ __align__(16) float Asf[32 * 132];          // 16896 B (k-major fp32 A)
    __shared__ __align__(16) float Bf [32 * 68];           // 8704 B  (k-major fp32 B stripe)

    const int tid  = threadIdx.x;
    const int wid  = tid >> 5, lane = tid & 31;
    const int row0 = blockIdx.x * 128;
    const int col0 = blockIdx.y * 128;                     // mma tile columns
    const int col0f = HB_N0 + blockIdx.y * 64;             // ffma stripe columns
    const bool fact = (blockIdx.y < HB_NF);

    // ---- mma role state (wid<8, tid<256) ----
    const int g    = lane >> 2, tig = lane & 3;
    const int q    = lane >> 3, r = lane & 7;
    const int warp_m = (wid >> 2) * 64;
    const int warp_n = (wid & 3) * 32;
    const int ldr = tid >> 2;          // valid for tid<256
    const int ldc = (tid & 3) * 8;
    const uint32_t as_base = (uint32_t)__cvta_generic_to_shared(As);
    const uint32_t bs_base = (uint32_t)__cvta_generic_to_shared(Bs);
    const uint32_t a_addr0 = as_base + (uint32_t)(((warp_m + (q & 1) * 8 + r) * 40 + (q >> 1) * 8) * 2);
    const uint32_t b_addr0 = bs_base + (uint32_t)(((warp_n + (q & 1) * 8 + r) * 40 + (q >> 1) * 8) * 2);

    const __nv_bfloat16* Ap0 = A + (size_t)(row0 + (tid < 256 ? ldr : 0)) * K + ldc;
    const __nv_bfloat16* Ap1 = A + (size_t)(row0 + (tid < 256 ? ldr : 0) + 64) * K + ldc;
    const __nv_bfloat16* Bp0 = B + (size_t)(col0 + (tid < 256 ? ldr : 0)) * K + ldc;
    const __nv_bfloat16* Bp1 = B + (size_t)(col0 + (tid < 256 ? ldr : 0) + 64) * K + ldc;

    float macc[16][4];
#pragma unroll
    for (int i = 0; i < 16; i++)
#pragma unroll
        for (int j = 0; j < 4; j++) macc[i][j] = 0.f;

    // ---- ffma role state (wid>=8) ----
    const int t2 = tid - 256;                 // 0..127
    const int fty = (t2 >> 3);                // 0..15 -> rows fty*8
    const int ftx = (t2 & 7);                 // 0..7  -> cols ftx*8
    const __nv_bfloat16* FA = A + (size_t)(row0 + (t2 < 0 ? 0 : t2)) * K;  // row t2
    const int fbrow = (t2 >> 1);              // 0..63
    const int fbkh  = (t2 & 1) * 16;          // 0 or 16
    const __nv_bfloat16* FB = fact ? (B + (size_t)(col0f + fbrow) * K + fbkh) : B;

    float facc[8][8];
#pragma unroll
    for (int i = 0; i < 8; i++)
#pragma unroll
        for (int j = 0; j < 8; j++) facc[i][j] = 0.f;

    // prologue prefetch (slab 0)
    uint4 pa0, pa1, pb0, pb1;       // mma
    uint4 fpa[4]; uint4 fpb[2];     // ffma
    if (tid < 256) {
        pa0 = *(const uint4*)Ap0;  pa1 = *(const uint4*)Ap1;
        pb0 = *(const uint4*)Bp0;  pb1 = *(const uint4*)Bp1;
    } else {
#pragma unroll
        for (int i = 0; i < 4; i++) fpa[i] = *(const uint4*)(FA + i * 8);
        if (fact) { fpb[0] = *(const uint4*)FB; fpb[1] = *(const uint4*)(FB + 8); }
    }

    for (int kb = 0; kb < K; kb += 32) {
        // ---------- store phase ----------
        if (tid < 256) {
            *(uint4*)&As[ldr * 40 + ldc]        = pa0;
            *(uint4*)&As[(ldr + 64) * 40 + ldc] = pa1;
            *(uint4*)&Bs[ldr * 40 + ldc]        = pb0;
            *(uint4*)&Bs[(ldr + 64) * 40 + ldc] = pb1;
        } else {
            // A row t2 -> Asf[k][t2] (fp32, k-major)
            const uint32_t* pw = (const uint32_t*)fpa;   // 16 u32 = 32 bf16
#pragma unroll
            for (int e = 0; e < 16; e++) {
                uint32_t u = pw[e];
                Asf[(e * 2 + 0) * 132 + t2] = __uint_as_float(u << 16);
                Asf[(e * 2 + 1) * 132 + t2] = __uint_as_float(u & 0xFFFF0000u);
            }
            if (fact) {
                const uint32_t* qw = (const uint32_t*)fpb;  // 8 u32 = 16 bf16
#pragma unroll
                for (int e = 0; e < 8; e++) {
                    uint32_t u = qw[e];
                    Bf[(fbkh + e * 2 + 0) * 68 + fbrow] = __uint_as_float(u << 16);
                    Bf[(fbkh + e * 2 + 1) * 68 + fbrow] = __uint_as_float(u & 0xFFFF0000u);
                }
            }
        }
        __syncthreads();

        // ---------- prefetch next slab ----------
        if (kb + 32 < K) {
            if (tid < 256) {
                pa0 = *(const uint4*)(Ap0 + kb + 32);
                pa1 = *(const uint4*)(Ap1 + kb + 32);
                pb0 = *(const uint4*)(Bp0 + kb + 32);
                pb1 = *(const uint4*)(Bp1 + kb + 32);
            } else {
#pragma unroll
                for (int i = 0; i < 4; i++) fpa[i] = *(const uint4*)(FA + kb + 32 + i * 8);
                if (fact) {
                    fpb[0] = *(const uint4*)(FB + kb + 32);
                    fpb[1] = *(const uint4*)(FB + kb + 40);
                }
            }
        }

        // ---------- compute phase ----------
        if (wid < 8) {
#pragma unroll
            for (int ks = 0; ks < 2; ks++) {
                uint32_t af[4][4], bfr[4][2];
#pragma unroll
                for (int mt = 0; mt < 4; mt++)
                    ldsm_x4(af[mt][0], af[mt][1], af[mt][2], af[mt][3],
                            a_addr0 + (uint32_t)((mt * 16 * 40 + ks * 16) * 2));
#pragma unroll
                for (int bt = 0; bt < 2; bt++) {
                    uint32_t m0, m1, m2, m3;
                    ldsm_x4(m0, m1, m2, m3,
                            b_addr0 + (uint32_t)((bt * 16 * 40 + ks * 16) * 2));
                    bfr[bt * 2 + 0][0] = m0; bfr[bt * 2 + 1][0] = m1;
                    bfr[bt * 2 + 0][1] = m2; bfr[bt * 2 + 1][1] = m3;
                }
#pragma unroll
                for (int mt = 0; mt < 4; mt++)
#pragma unroll
                    for (int nt = 0; nt < 4; nt++)
                        mma_bf16(macc[mt * 4 + nt], af[mt], bfr[nt]);
            }
        } else if (fact) {
#pragma unroll 2
            for (int k = 0; k < 32; k++) {
                float4 a0 = *(const float4*)&Asf[k * 132 + fty * 8];
                float4 a1 = *(const float4*)&Asf[k * 132 + fty * 8 + 4];
                float4 b0 = *(const float4*)&Bf [k * 68  + ftx * 8];
                float4 b1 = *(const float4*)&Bf [k * 68  + ftx * 8 + 4];
                float a[8] = {a0.x, a0.y, a0.z, a0.w, a1.x, a1.y, a1.z, a1.w};
                float b[8] = {b0.x, b0.y, b0.z, b0.w, b1.x, b1.y, b1.z, b1.w};
#pragma unroll
                for (int i = 0; i < 8; i++)
#pragma unroll
                    for (int j = 0; j < 8; j++)
                        facc[i][j] = fmaf(a[i], b[j], facc[i][j]);
            }
        }
        __syncthreads();
    }

    // ---------- epilogues (remap always: proj writes [B,T] order) ----------
    if (wid < 8) {
#pragma unroll
        for (int mt = 0; mt < 4; mt++) {
            int m0 = row0 + warp_m + mt * 16 + g;
            int m1 = m0 + 8;
            int r0 = (m0 & 3) * Tlen + (m0 >> 2);
            int r1 = (m1 & 3) * Tlen + (m1 >> 2);
#pragma unroll
            for (int nt = 0; nt < 4; nt++) {
                int n = col0 + warp_n + nt * 8 + tig * 2;
                float* c = macc[mt * 4 + nt];
                *(float2*)&C[(size_t)r0 * N + n] = make_float2(c[0], c[1]);
                *(float2*)&C[(size_t)r1 * N + n] = make_float2(c[2], c[3]);
            }
        }
    } else if (fact) {
#pragma unroll
        for (int i = 0; i < 8; i++) {
            int m = row0 + fty * 8 + i;
            int orow = (m & 3) * Tlen + (m >> 2);
            float* crow = C + (size_t)orow * N + col0f + ftx * 8;
            *(float4*)(crow)     = make_float4(facc[i][0], facc[i][1], facc[i][2], facc[i][3]);
            *(float4*)(crow + 4) = make_float4(facc[i][4], facc[i][5], facc[i][6], facc[i][7]);
        }
    }
}

// ---------------- persistent LSTM layer (round-12 proven) ----------------
__global__ void __launch_bounds__(256, 1)
lstm_layer(const float* __restrict__ gih,
           const float* __restrict__ Whh,
           __nv_bfloat16* __restrict__ hbf)
{
    __shared__ __align__(16) float hs[4 * Edim];
    __shared__ float garr[128];
    __shared__ float cs[32];

    const int blk  = blockIdx.x;
    const int e0   = blk * 8;
    const int tid  = threadIdx.x;
    const int warp = tid >> 5;
    const int lane = tid & 31;

    unsigned long long wreg[4][16];
#pragma unroll
    for (int rr = 0; rr < 4; rr++) {
        int r = warp * 4 + rr, g = r >> 3, j = r & 7;
        const float* src = Whh + (size_t)(g * Edim + e0 + j) * Edim;
#pragma unroll
        for (int jj = 0; jj < 16; jj++) {
            int kp = lane + 32 * jj;
            float2 v = *(const float2*)&src[kp * 2];
            wreg[rr][jj] = packf2(v.x, v.y);
        }
    }
    if (tid < 32) cs[tid] = 0.f;
    __syncthreads();

    for (int t = 0; t < Tlen; t++) {
        if (t == 0) {
            for (int i = tid; i < 4 * Edim; i += 256) hs[i] = 0.f;
        } else {
            const uint4* hp = (const uint4*)(hbf + (size_t)t * (Bsz * Edim));
#pragma unroll
            for (int i = tid; i < 512; i += 256) {
                uint4 p = hp[i];
                float* d = hs + i * 8;
                d[0] = __uint_as_float(p.x << 16);
                d[1] = __uint_as_float(p.x & 0xFFFF0000u);
                d[2] = __uint_as_float(p.y << 16);
                d[3] = __uint_as_float(p.y & 0xFFFF0000u);
                d[4] = __uint_as_float(p.z << 16);
                d[5] = __uint_as_float(p.z & 0xFFFF0000u);
                d[6] = __uint_as_float(p.w << 16);
                d[7] = __uint_as_float(p.w & 0xFFFF0000u);
            }
        }
        __syncthreads();

        unsigned long long acc[16];
#pragma unroll
        for (int i = 0; i < 16; i++) acc[i] = 0ull;

#pragma unroll
        for (int jj = 0; jj < 16; jj++) {
            int kp = lane + 32 * jj;
            unsigned long long H0 = *(const unsigned long long*)&hs[kp * 2];
            unsigned long long H1 = *(const unsigned long long*)&hs[Edim + kp * 2];
            unsigned long long H2 = *(const unsigned long long*)&hs[2 * Edim + kp * 2];
            unsigned long long H3 = *(const unsigned long long*)&hs[3 * Edim + kp * 2];
            fma2(acc[ 0], wreg[0][jj], H0); fma2(acc[ 1], wreg[0][jj], H1);
            fma2(acc[ 2], wreg[0][jj], H2); fma2(acc[ 3], wreg[0][jj], H3);
            fma2(acc[ 4], wreg[1][jj], H0); fma2(acc[ 5], wreg[1][jj], H1);
            fma2(acc[ 6], wreg[1][jj], H2); fma2(acc[ 7], wreg[1][jj], H3);
            fma2(acc[ 8], wreg[2][jj], H0); fma2(acc[ 9], wreg[2][jj], H1);
            fma2(acc[10], wreg[2][jj], H2); fma2(acc[11], wreg[2][jj], H3);
            fma2(acc[12], wreg[3][jj], H0); fma2(acc[13], wreg[3][jj], H1);
            fma2(acc[14], wreg[3][jj], H2); fma2(acc[15], wreg[3][jj], H3);
        }

        float a[16];
#pragma unroll
        for (int i = 0; i < 16; i++) a[i] = f2sum(acc[i]);
#pragma unroll
        for (int off = 16; off; off >>= 1)
#pragma unroll
            for (int i = 0; i < 16; i++)
                a[i] += __shfl_down_sync(~0u, a[i], off);

        if (lane == 0) {
#pragma unroll
            for (int rr = 0; rr < 4; rr++) {
                int r = warp * 4 + rr, g = r >> 3, j = r & 7;
#pragma unroll
                for (int b = 0; b < 4; b++)
                    garr[(g * 4 + b) * 8 + j] = a[rr * 4 + b];
            }
        }
        __syncthreads();

        if (tid < 32) {
            int b = tid >> 3, j = tid & 7, e = e0 + j;
            const float* gb = gih + ((size_t)t * Bsz + b) * GDIM;
            float gi = garr[(0 * 4 + b) * 8 + j] + gb[e];
            float gf = garr[(1 * 4 + b) * 8 + j] + gb[Edim + e];
            float gG = garr[(2 * 4 + b) * 8 + j] + gb[2 * Edim + e];
            float go = garr[(3 * 4 + b) * 8 + j] + gb[3 * Edim + e];
            float c = sigm(gf) * cs[tid] + sigm(gi) * tanh_acc(gG);
            cs[tid] = c;
            float hv = sigm(go) * tanh_acc(c);
            hbf[(size_t)(t + 1) * (Bsz * Edim) + b * Edim + e] = __float2bfloat16(hv);
        }
        __syncthreads();

        if (tid == 0) grid_barrier_t0((unsigned int)(t + 1));
        __syncthreads();
    }
}

// ---------------- post-processing (round-12 proven) ----------------
__global__ void postprocess(float* __restrict__ out) {
    const int r = blockIdx.x;
    const int t_idx = r & (Tlen - 1);
    float* z = out + (size_t)r * Vdim;
    const int tid = threadIdx.x;

    __shared__ float redm[256];
    __shared__ float reds[256];
    __shared__ float sh_shift, sh_eos;

    float m = -3.402823466e38f, s = 0.f;
    const float4* z4 = (const float4*)z;
    for (int i = tid; i < 7999; i += 256) {
        float4 v = z4[i];
        float mv = fmaxf(fmaxf(v.x, v.y), fmaxf(v.z, v.w));
        float m2 = fmaxf(m, mv);
        s = s * expf(m - m2)
          + expf(v.x - m2) + expf(v.y - m2) + expf(v.z - m2) + expf(v.w - m2);
        m = m2;
    }
    if (tid < 3) {
        float x = z[31996 + tid];
        float m2 = fmaxf(m, x);
        s = s * expf(m - m2) + expf(x - m2);
        m = m2;
    }
    redm[tid] = m; reds[tid] = s;
    __syncthreads();
#pragma unroll
    for (int st = 128; st; st >>= 1) {
        if (tid < st) {
            float mo = redm[tid], so = reds[tid];
            float mn = redm[tid + st], sn = reds[tid + st];
            float mm = fmaxf(mo, mn);
            redm[tid] = mm;
            reds[tid] = so * expf(mo - mm) + sn * expf(mn - mm);
        }
        __syncthreads();
    }

    if (tid == 0) {
        double lse = (double)redm[0] + log((double)reds[0]);
        double e   = (double)z[Vdim - 1];
        double lsn = (-e < 0 ? -e : 0.0) - log1p(exp(-fabs(e)));
        double lsp = ( e < 0 ?  e : 0.0) - log1p(exp(-fabs(e)));
        double log_lb = (double)(t_idx + 1) * LOGB;
        double C1 = log_lb + lsn;
        double log_lb_eos = log(-expm1(log_lb)) + lsn;
        double d = log_lb_eos - lsp;
        double logsig_d = (d < 0 ? d : 0.0) - log1p(exp(-fabs(d)));
        double lpe = log_lb_eos - logsig_d;
        double m2 = fmax(C1, lpe);
        double Z  = m2 + log1p(exp(fmin(C1, lpe) - m2));
        sh_shift = (float)(C1 - lse - Z);
        sh_eos   = (float)(lpe - Z);
    }
    __syncthreads();

    float shift = sh_shift;
    float4* zw = (float4*)z;
    for (int i = tid; i < 7999; i += 256) {
        float4 v = zw[i];
        v.x += shift; v.y += shift; v.z += shift; v.w += shift;
        zw[i] = v;
    }
    if (tid < 3) z[31996 + tid] += shift;
    if (tid == 0) z[Vdim - 1] = sh_eos;
}

// ---------------- launcher ----------------
extern "C" void kernel_launch(void* const* d_in, const int* in_sizes, int n_in,
                              void* d_out, int out_size)
{
    (void)in_sizes; (void)n_in; (void)out_size;
    // 0:tokens 1:emb 2:Wproj 3:Wih0 4:Whh0 5:bih0 6:bhh0 7:Wih1 8:Whh1 9:bih1 10:bhh1
    const int*   tokens = (const int*)  d_in[0];
    const float* emb    = (const float*)d_in[1];
    const float* Wproj  = (const float*)d_in[2];
    const float* Wih0   = (const float*)d_in[3];
    const float* Whh0   = (const float*)d_in[4];
    const float* bih0   = (const float*)d_in[5];
    const float* bhh0   = (const float*)d_in[6];
    const float* Wih1   = (const float*)d_in[7];
    const float* Whh1   = (const float*)d_in[8];
    const float* bih1   = (const float*)d_in[9];
    const float* bhh1   = (const float*)d_in[10];
    float* out = (float*)d_out;

    __nv_bfloat16 *pxbf, *ph0bf, *ph1bf, *pw0, *pw1, *pwp;
    float *pg;
    cudaGetSymbolAddress((void**)&pxbf,  g_xbf);
    cudaGetSymbolAddress((void**)&pg,    g_gates);
    cudaGetSymbolAddress((void**)&ph0bf, g_h0bf);
    cudaGetSymbolAddress((void**)&ph1bf, g_h1bf);
    cudaGetSymbolAddress((void**)&pw0,   g_wih0bf);
    cudaGetSymbolAddress((void**)&pw1,   g_wih1bf);
    cudaGetSymbolAddress((void**)&pwp,   g_wprojbf);

    // 0. weight conversions
    f2bf_kernel<<<GDIM * Edim / 1024, 256>>>(Wih0, pw0, GDIM * Edim);
    f2bf_kernel<<<GDIM * Edim / 1024, 256>>>(Wih1, pw1, GDIM * Edim);
    f2bf_kernel<<<Vdim * (Edim / 1024), 256>>>(Wproj, pwp, Vdim * Edim);

    // 1. embedding
    embed_kernel<<<(MROWS * Edim / 4 + 255) / 256, 256>>>(tokens, emb);

    // 2. layer-0 input gates (bf16 tensor cores)
    dim3 gg(MROWS / 128, GDIM / 128);
    gemm_bf16_nt<<<gg, 256>>>(pxbf, pw0, pg, MROWS, GDIM, Edim, bih0, bhh0, 0);

    // 3. layer-0 recurrence
    bar_reset<<<1, 1>>>();
    lstm_layer<<<NBLK, 256>>>(pg, Whh0, ph0bf);

    // 4. layer-1 input gates
    gemm_bf16_nt<<<gg, 256>>>(ph0bf + Bsz * Edim, pw1, pg, MROWS, GDIM, Edim, bih1, bhh1, 0);

    // 5. layer-1 recurrence
    bar_reset<<<1, 1>>>();
    lstm_layer<<<NBLK, 256>>>(pg, Whh1, ph1bf);

    // 6. projection (hybrid mma+ffma, both pipes) -> d_out with [B,T] remap
    dim3 gp(MROWS / 128, HB_CM);            // (16, 167)
    gemm_hybrid<<<gp, 384>>>(ph1bf + Bsz * Edim, pwp, out, MROWS, Vdim, Edim);

    // 7. post-processing
    postprocess<<<MROWS, 256>>>(out);
}

// round 14
// speedup vs baseline: 1.3370x; 1.3370x over previous
#include <cuda_runtime.h>
#include <cuda_fp16.h>
#include <math.h>
#include <stdint.h>

#define Bsz  4
#define Tlen 512
#define Edim 1024
#define Vdim 32000
#define GDIM (4*Edim)           // 4096
#define MROWS (Tlen*Bsz)        // 2048
#define NBLK 128
#define LOGB (-1.0005003335835335e-3)

// ---------------- scratch ----------------
static __device__ __align__(16) __half g_xh [MROWS * Edim];
static __device__ __align__(16) float  g_gates[MROWS * GDIM];
static __device__ __align__(16) __half g_h0h[(Tlen+1) * Bsz*Edim];
static __device__ __align__(16) __half g_h1h[(Tlen+1) * Bsz*Edim];
static __device__ __align__(16) __half g_wih0h[GDIM * Edim];
static __device__ __align__(16) __half g_wih1h[GDIM * Edim];
static __device__ __align__(16) __half g_wprojh[(size_t)Vdim * Edim];

// grid-barrier (proven)
static __device__ unsigned int g_arrive;
static __device__ unsigned int g_release;
__global__ void bar_reset() { g_arrive = 0; g_release = 0; }

// ---------------- helpers ----------------
__device__ __forceinline__ float tanh_acc(float x) {
    float ax = fabsf(x);
    float t  = expf(-2.f * ax);
    float r  = (1.f - t) / (1.f + t);
    return copysignf(r, x);
}
__device__ __forceinline__ float sigm(float x) { return 1.f / (1.f + expf(-x)); }

__device__ __forceinline__ void grid_barrier_t0(unsigned int gen) {
    __threadfence();
    unsigned int prev = atomicAdd(&g_arrive, 1u);
    if (prev + 1u == gen * NBLK) {
        __threadfence();
        asm volatile("st.release.gpu.u32 [%0], %1;"
                     :: "l"(&g_release), "r"(gen) : "memory");
    } else {
        unsigned int v;
        do {
            asm volatile("ld.acquire.gpu.u32 %0, [%1];"
                         : "=r"(v) : "l"(&g_release) : "memory");
        } while (v < gen);
    }
}

__device__ __forceinline__ void fma2(unsigned long long& acc,
                                     unsigned long long a, unsigned long long b) {
    asm("fma.rn.f32x2 %0, %1, %2, %0;" : "+l"(acc) : "l"(a), "l"(b));
}
__device__ __forceinline__ float f2sum(unsigned long long acc) {
    uint32_t lo, hi;
    asm("mov.b64 {%0,%1}, %2;" : "=r"(lo), "=r"(hi) : "l"(acc));
    return __uint_as_float(lo) + __uint_as_float(hi);
}
__device__ __forceinline__ unsigned long long packf2(float a, float b) {
    unsigned long long r;
    asm("mov.b64 %0, {%1,%2};" : "=l"(r) : "f"(a), "f"(b));
    return r;
}
__device__ __forceinline__ uint32_t packh2(float a, float b) {
    __half2 t = __floats2half2_rn(a, b);
    return *(uint32_t*)&t;
}

__device__ __forceinline__ void ldsm_x4(uint32_t& r0, uint32_t& r1, uint32_t& r2, uint32_t& r3,
                                        uint32_t addr) {
    asm volatile("ldmatrix.sync.aligned.m8n8.x4.shared.b16 {%0,%1,%2,%3}, [%4];"
                 : "=r"(r0), "=r"(r1), "=r"(r2), "=r"(r3) : "r"(addr));
}
// f16 x f16 -> f16 accumulate (packed: 2 u32 = 4 halves)
__device__ __forceinline__ void mma_f16acc(uint32_t c[2], const uint32_t a[4], const uint32_t b[2]) {
    asm volatile(
        "mma.sync.aligned.m16n8k16.row.col.f16.f16.f16.f16 "
        "{%0,%1}, {%2,%3,%4,%5}, {%6,%7}, {%0,%1};"
        : "+r"(c[0]), "+r"(c[1])
        : "r"(a[0]), "r"(a[1]), "r"(a[2]), "r"(a[3]), "r"(b[0]), "r"(b[1]));
}

// ---------------- fp32 -> fp16 conversion ----------------
__global__ void f2h_kernel(const float* __restrict__ s, __half* __restrict__ d, int n) {
    int idx = (blockIdx.x * blockDim.x + threadIdx.x) * 4;
    if (idx >= n) return;
    float4 v = *(const float4*)(s + idx);
    uint2 p;
    p.x = packh2(v.x, v.y); p.y = packh2(v.z, v.w);
    *(uint2*)(d + idx) = p;
}

// ---------------- embedding -> fp16 ----------------
__global__ void embed_kernel(const int* __restrict__ tokens, const float* __restrict__ emb) {
    int id = blockIdx.x * blockDim.x + threadIdx.x;
    const int EV = Edim / 4;
    if (id >= MROWS * EV) return;
    int e4 = id % EV;
    int m  = id / EV;
    int b  = m & 3, t = m >> 2;
    int tok = tokens[b * Tlen + t];
    float4 v = ((const float4*)(emb + (size_t)tok * Edim))[e4];
    uint2 p; p.x = packh2(v.x, v.y); p.y = packh2(v.z, v.w);
    *(uint2*)(g_xh + (size_t)id * 4) = p;
}

// ---------------- fp16 tensor-core GEMM (NT), f16 accumulate with
// fp32 promotion every K=128 chunk ----------------
__global__ __launch_bounds__(256)
void gemm_f16_nt(const __half* __restrict__ A, const __half* __restrict__ B,
                 float* __restrict__ C, int M, int N, int K,
                 const float* __restrict__ bias1, const float* __restrict__ bias2,
                 int remap)
{
    __shared__ __align__(16) __half As[128 * 40];
    __shared__ __align__(16) __half Bs[128 * 40];
    const int tid  = threadIdx.x;
    const int wid  = tid >> 5, lane = tid & 31;
    const int g    = lane >> 2, tig = lane & 3;
    const int q    = lane >> 3, r = lane & 7;
    const int warp_m = (wid >> 2) * 64;
    const int warp_n = (wid & 3) * 32;
    const int row0 = blockIdx.x * 128;
    const int col0 = blockIdx.y * 128;

    const int ldr = tid >> 2;
    const int ldc = (tid & 3) * 8;

    const __half* Ap0 = A + (size_t)(row0 + ldr) * K + ldc;
    const __half* Ap1 = A + (size_t)(row0 + ldr + 64) * K + ldc;
    const __half* Bp0 = B + (size_t)(col0 + ldr) * K + ldc;
    const __half* Bp1 = B + (size_t)(col0 + ldr + 64) * K + ldc;

    const uint32_t as_base = (uint32_t)__cvta_generic_to_shared(As);
    const uint32_t bs_base = (uint32_t)__cvta_generic_to_shared(Bs);
    const uint32_t a_addr0 = as_base + (uint32_t)(((warp_m + (q & 1) * 8 + r) * 40 + (q >> 1) * 8) * 2);
    const uint32_t b_addr0 = bs_base + (uint32_t)(((warp_n + (q & 1) * 8 + r) * 40 + (q >> 1) * 8) * 2);

    uint32_t hacc[16][2];          // f16x2 accumulators
    float    facc[16][4];          // fp32 chunk-promoted accumulators
#pragma unroll
    for (int i = 0; i < 16; i++) {
        hacc[i][0] = 0u; hacc[i][1] = 0u;
#pragma unroll
        for (int j = 0; j < 4; j++) facc[i][j] = 0.f;
    }

    uint4 pa0 = *(const uint4*)Ap0;
    uint4 pa1 = *(const uint4*)Ap1;
    uint4 pb0 = *(const uint4*)Bp0;
    uint4 pb1 = *(const uint4*)Bp1;

    for (int kb = 0; kb < K; kb += 32) {
        *(uint4*)&As[ldr * 40 + ldc]        = pa0;
        *(uint4*)&As[(ldr + 64) * 40 + ldc] = pa1;
        *(uint4*)&Bs[ldr * 40 + ldc]        = pb0;
        *(uint4*)&Bs[(ldr + 64) * 40 + ldc] = pb1;
        __syncthreads();

        if (kb + 32 < K) {
            pa0 = *(const uint4*)(Ap0 + kb + 32);
            pa1 = *(const uint4*)(Ap1 + kb + 32);
            pb0 = *(const uint4*)(Bp0 + kb + 32);
            pb1 = *(const uint4*)(Bp1 + kb + 32);
        }

#pragma unroll
        for (int ks = 0; ks < 2; ks++) {
            uint32_t af[4][4], bf[4][2];
#pragma unroll
            for (int mt = 0; mt < 4; mt++)
                ldsm_x4(af[mt][0], af[mt][1], af[mt][2], af[mt][3],
                        a_addr0 + (uint32_t)((mt * 16 * 40 + ks * 16) * 2));
#pragma unroll
            for (int bt = 0; bt < 2; bt++) {
                uint32_t m0, m1, m2, m3;
                ldsm_x4(m0, m1, m2, m3,
                        b_addr0 + (uint32_t)((bt * 16 * 40 + ks * 16) * 2));
                bf[bt * 2 + 0][0] = m0; bf[bt * 2 + 1][0] = m1;
                bf[bt * 2 + 0][1] = m2; bf[bt * 2 + 1][1] = m3;
            }
#pragma unroll
            for (int mt = 0; mt < 4; mt++)
#pragma unroll
                for (int nt = 0; nt < 4; nt++)
                    mma_f16acc(hacc[mt * 4 + nt], af[mt], bf[nt]);
        }

        // promote f16 accumulators to fp32 every K=128 chunk
        if (((kb >> 5) & 3) == 3) {
#pragma unroll
            for (int i = 0; i < 16; i++) {
                float2 lo = __half22float2(*(__half2*)&hacc[i][0]);
                float2 hi = __half22float2(*(__half2*)&hacc[i][1]);
                facc[i][0] += lo.x; facc[i][1] += lo.y;
                facc[i][2] += hi.x; facc[i][3] += hi.y;
                hacc[i][0] = 0u; hacc[i][1] = 0u;
            }
        }
        __syncthreads();
    }

#pragma unroll
    for (int mt = 0; mt < 4; mt++) {
        int m0 = row0 + warp_m + mt * 16 + g;
        int m1 = m0 + 8;
        int r0 = remap ? ((m0 & 3) * Tlen + (m0 >> 2)) : m0;
        int r1 = remap ? ((m1 & 3) * Tlen + (m1 >> 2)) : m1;
#pragma unroll
        for (int nt = 0; nt < 4; nt++) {
            int n = col0 + warp_n + nt * 8 + tig * 2;
            float bv0 = 0.f, bv1 = 0.f;
            if (bias1) { bv0 += bias1[n]; bv1 += bias1[n + 1]; }
            if (bias2) { bv0 += bias2[n]; bv1 += bias2[n + 1]; }
            float* c = facc[mt * 4 + nt];
            *(float2*)&C[(size_t)r0 * N + n] = make_float2(c[0] + bv0, c[1] + bv1);
            *(float2*)&C[(size_t)r1 * N + n] = make_float2(c[2] + bv0, c[3] + bv1);
        }
    }
}

// ---------------- persistent LSTM layer (round-12 proven; h stored fp16) ----------------
__global__ void __launch_bounds__(256, 1)
lstm_layer(const float* __restrict__ gih,
           const float* __restrict__ Whh,
           __half* __restrict__ hh)          // [T+1,B,E] fp16
{
    __shared__ __align__(16) float hs[4 * Edim];
    __shared__ float garr[128];
    __shared__ float cs[32];

    const int blk  = blockIdx.x;
    const int e0   = blk * 8;
    const int tid  = threadIdx.x;
    const int warp = tid >> 5;
    const int lane = tid & 31;

    unsigned long long wreg[4][16];
#pragma unroll
    for (int rr = 0; rr < 4; rr++) {
        int r = warp * 4 + rr, g = r >> 3, j = r & 7;
        const float* src = Whh + (size_t)(g * Edim + e0 + j) * Edim;
#pragma unroll
        for (int jj = 0; jj < 16; jj++) {
            int kp = lane + 32 * jj;
            float2 v = *(const float2*)&src[kp * 2];
            wreg[rr][jj] = packf2(v.x, v.y);
        }
    }
    if (tid < 32) cs[tid] = 0.f;
    __syncthreads();

    for (int t = 0; t < Tlen; t++) {
        if (t == 0) {
            for (int i = tid; i < 4 * Edim; i += 256) hs[i] = 0.f;
        } else {
            const uint4* hp = (const uint4*)(hh + (size_t)t * (Bsz * Edim));
#pragma unroll
            for (int i = tid; i < 512; i += 256) {
                uint4 p = hp[i];                        // 8 fp16
                float* d = hs + i * 8;
                float2 f0 = __half22float2(*(__half2*)&p.x);
                float2 f1 = __half22float2(*(__half2*)&p.y);
                float2 f2 = __half22float2(*(__half2*)&p.z);
                float2 f3 = __half22float2(*(__half2*)&p.w);
                d[0] = f0.x; d[1] = f0.y; d[2] = f1.x; d[3] = f1.y;
                d[4] = f2.x; d[5] = f2.y; d[6] = f3.x; d[7] = f3.y;
            }
        }
        __syncthreads();

        unsigned long long acc[16];
#pragma unroll
        for (int i = 0; i < 16; i++) acc[i] = 0ull;

#pragma unroll
        for (int jj = 0; jj < 16; jj++) {
            int kp = lane + 32 * jj;
            unsigned long long H0 = *(const unsigned long long*)&hs[kp * 2];
            unsigned long long H1 = *(const unsigned long long*)&hs[Edim + kp * 2];
            unsigned long long H2 = *(const unsigned long long*)&hs[2 * Edim + kp * 2];
            unsigned long long H3 = *(const unsigned long long*)&hs[3 * Edim + kp * 2];
            fma2(acc[ 0], wreg[0][jj], H0); fma2(acc[ 1], wreg[0][jj], H1);
            fma2(acc[ 2], wreg[0][jj], H2); fma2(acc[ 3], wreg[0][jj], H3);
            fma2(acc[ 4], wreg[1][jj], H0); fma2(acc[ 5], wreg[1][jj], H1);
            fma2(acc[ 6], wreg[1][jj], H2); fma2(acc[ 7], wreg[1][jj], H3);
            fma2(acc[ 8], wreg[2][jj], H0); fma2(acc[ 9], wreg[2][jj], H1);
            fma2(acc[10], wreg[2][jj], H2); fma2(acc[11], wreg[2][jj], H3);
            fma2(acc[12], wreg[3][jj], H0); fma2(acc[13], wreg[3][jj], H1);
            fma2(acc[14], wreg[3][jj], H2); fma2(acc[15], wreg[3][jj], H3);
        }

        float a[16];
#pragma unroll
        for (int i = 0; i < 16; i++) a[i] = f2sum(acc[i]);
#pragma unroll
        for (int off = 16; off; off >>= 1)
#pragma unroll
            for (int i = 0; i < 16; i++)
                a[i] += __shfl_down_sync(~0u, a[i], off);

        if (lane == 0) {
#pragma unroll
            for (int rr = 0; rr < 4; rr++) {
                int r = warp * 4 + rr, g = r >> 3, j = r & 7;
#pragma unroll
                for (int b = 0; b < 4; b++)
                    garr[(g * 4 + b) * 8 + j] = a[rr * 4 + b];
            }
        }
        __syncthreads();

        if (tid < 32) {
            int b = tid >> 3, j = tid & 7, e = e0 + j;
            const float* gb = gih + ((size_t)t * Bsz + b) * GDIM;
            float gi = garr[(0 * 4 + b) * 8 + j] + gb[e];
            float gf = garr[(1 * 4 + b) * 8 + j] + gb[Edim + e];
            float gG = garr[(2 * 4 + b) * 8 + j] + gb[2 * Edim + e];
            float go = garr[(3 * 4 + b) * 8 + j] + gb[3 * Edim + e];
            float c = sigm(gf) * cs[tid] + sigm(gi) * tanh_acc(gG);
            cs[tid] = c;
            float hv = sigm(go) * tanh_acc(c);
            hh[(size_t)(t + 1) * (Bsz * Edim) + b * Edim + e] = __float2half(hv);
        }
        __syncthreads();

        if (tid == 0) grid_barrier_t0((unsigned int)(t + 1));
        __syncthreads();
    }
}

// ---------------- post-processing (round-12 proven) ----------------
__global__ void postprocess(float* __restrict__ out) {
    const int r = blockIdx.x;
    const int t_idx = r & (Tlen - 1);
    float* z = out + (size_t)r * Vdim;
    const int tid = threadIdx.x;

    __shared__ float redm[256];
    __shared__ float reds[256];
    __shared__ float sh_shift, sh_eos;

    float m = -3.402823466e38f, s = 0.f;
    const float4* z4 = (const float4*)z;
    for (int i = tid; i < 7999; i += 256) {
        float4 v = z4[i];
        float mv = fmaxf(fmaxf(v.x, v.y), fmaxf(v.z, v.w));
        float m2 = fmaxf(m, mv);
        s = s * expf(m - m2)
          + expf(v.x - m2) + expf(v.y - m2) + expf(v.z - m2) + expf(v.w - m2);
        m = m2;
    }
    if (tid < 3) {
        float x = z[31996 + tid];
        float m2 = fmaxf(m, x);
        s = s * expf(m - m2) + expf(x - m2);
        m = m2;
    }
    redm[tid] = m; reds[tid] = s;
    __syncthreads();
#pragma unroll
    for (int st = 128; st; st >>= 1) {
        if (tid < st) {
            float mo = redm[tid], so = reds[tid];
            float mn = redm[tid + st], sn = reds[tid + st];
            float mm = fmaxf(mo, mn);
            redm[tid] = mm;
            reds[tid] = so * expf(mo - mm) + sn * expf(mn - mm);
        }
        __syncthreads();
    }

    if (tid == 0) {
        double lse = (double)redm[0] + log((double)reds[0]);
        double e   = (double)z[Vdim - 1];
        double lsn = (-e < 0 ? -e : 0.0) - log1p(exp(-fabs(e)));
        double lsp = ( e < 0 ?  e : 0.0) - log1p(exp(-fabs(e)));
        double log_lb = (double)(t_idx + 1) * LOGB;
        double C1 = log_lb + lsn;
        double log_lb_eos = log(-expm1(log_lb)) + lsn;
        double d = log_lb_eos - lsp;
        double logsig_d = (d < 0 ? d : 0.0) - log1p(exp(-fabs(d)));
        double lpe = log_lb_eos - logsig_d;
        double m2 = fmax(C1, lpe);
        double Z  = m2 + log1p(exp(fmin(C1, lpe) - m2));
        sh_shift = (float)(C1 - lse - Z);
        sh_eos   = (float)(lpe - Z);
    }
    __syncthreads();

    float shift = sh_shift;
    float4* zw = (float4*)z;
    for (int i = tid; i < 7999; i += 256) {
        float4 v = zw[i];
        v.x += shift; v.y += shift; v.z += shift; v.w += shift;
        zw[i] = v;
    }
    if (tid < 3) z[31996 + tid] += shift;
    if (tid == 0) z[Vdim - 1] = sh_eos;
}

// ---------------- launcher ----------------
extern "C" void kernel_launch(void* const* d_in, const int* in_sizes, int n_in,
                              void* d_out, int out_size)
{
    (void)in_sizes; (void)n_in; (void)out_size;
    // 0:tokens 1:emb 2:Wproj 3:Wih0 4:Whh0 5:bih0 6:bhh0 7:Wih1 8:Whh1 9:bih1 10:bhh1
    const int*   tokens = (const int*)  d_in[0];
    const float* emb    = (const float*)d_in[1];
    const float* Wproj  = (const float*)d_in[2];
    const float* Wih0   = (const float*)d_in[3];
    const float* Whh0   = (const float*)d_in[4];
    const float* bih0   = (const float*)d_in[5];
    const float* bhh0   = (const float*)d_in[6];
    const float* Wih1   = (const float*)d_in[7];
    const float* Whh1   = (const float*)d_in[8];
    const float* bih1   = (const float*)d_in[9];
    const float* bhh1   = (const float*)d_in[10];
    float* out = (float*)d_out;

    __half *pxh, *ph0h, *ph1h, *pw0, *pw1, *pwp;
    float *pg;
    cudaGetSymbolAddress((void**)&pxh,  g_xh);
    cudaGetSymbolAddress((void**)&pg,   g_gates);
    cudaGetSymbolAddress((void**)&ph0h, g_h0h);
    cudaGetSymbolAddress((void**)&ph1h, g_h1h);
    cudaGetSymbolAddress((void**)&pw0,  g_wih0h);
    cudaGetSymbolAddress((void**)&pw1,  g_wih1h);
    cudaGetSymbolAddress((void**)&pwp,  g_wprojh);

    // 0. weight conversions (fp32 -> fp16)
    f2h_kernel<<<GDIM * Edim / 1024, 256>>>(Wih0, pw0, GDIM * Edim);
    f2h_kernel<<<GDIM * Edim / 1024, 256>>>(Wih1, pw1, GDIM * Edim);
    f2h_kernel<<<Vdim * (Edim / 1024), 256>>>(Wproj, pwp, Vdim * Edim);

    // 1. embedding (fp16 out)
    embed_kernel<<<(MROWS * Edim / 4 + 255) / 256, 256>>>(tokens, emb);

    // 2. layer-0 input gates (fp16 mma, f16 acc + chunked fp32 promotion)
    dim3 gg(MROWS / 128, GDIM / 128);
    gemm_f16_nt<<<gg, 256>>>(pxh, pw0, pg, MROWS, GDIM, Edim, bih0, bhh0, 0);

    // 3. layer-0 recurrence
    bar_reset<<<1, 1>>>();
    lstm_layer<<<NBLK, 256>>>(pg, Whh0, ph0h);

    // 4. layer-1 input gates
    gemm_f16_nt<<<gg, 256>>>(ph0h + Bsz * Edim, pw1, pg, MROWS, GDIM, Edim, bih1, bhh1, 0);

    // 5. layer-1 recurrence
    bar_reset<<<1, 1>>>();
    lstm_layer<<<NBLK, 256>>>(pg, Whh1, ph1h);

    // 6. projection -> d_out with [B,T] remap
    dim3 gp(MROWS / 128, Vdim / 128);
    gemm_f16_nt<<<gp, 256>>>(ph1h + Bsz * Edim, pwp, out, MROWS, Vdim, Edim,
                             nullptr, nullptr, 1);

    // 7. post-processing
    postprocess<<<MROWS, 256>>>(out);
}

// round 15
// speedup vs baseline: 1.4761x; 1.1040x over previous
#include <cuda_runtime.h>
#include <cuda_bf16.h>
#include <math.h>
#include <stdint.h>

#define Bsz  4
#define Tlen 512
#define Edim 1024
#define Vdim 32000
#define GDIM (4*Edim)           // 4096
#define MROWS (Tlen*Bsz)        // 2048
#define NBLK 128
#define LOGB (-1.0005003335835335e-3)

// ---------------- scratch ----------------
static __device__ __align__(16) __nv_bfloat16 g_xbf [MROWS * Edim];
static __device__ __align__(16) float g_gates[MROWS * GDIM];
static __device__ __align__(16) __nv_bfloat16 g_h0bf[(Tlen+1) * Bsz*Edim];
static __device__ __align__(16) __nv_bfloat16 g_h1bf[(Tlen+1) * Bsz*Edim];
static __device__ __align__(16) __nv_bfloat16 g_wih0bf[GDIM * Edim];
static __device__ __align__(16) __nv_bfloat16 g_wih1bf[GDIM * Edim];
static __device__ __align__(16) __nv_bfloat16 g_wprojbf[(size_t)Vdim * Edim];

// grid-barrier (proven)
static __device__ unsigned int g_arrive;
static __device__ unsigned int g_release;
__global__ void bar_reset() { g_arrive = 0; g_release = 0; }

// ---------------- helpers ----------------
__device__ __forceinline__ float tanh_acc(float x) {
    float ax = fabsf(x);
    float t  = expf(-2.f * ax);
    float r  = (1.f - t) / (1.f + t);
    return copysignf(r, x);
}
__device__ __forceinline__ float sigm(float x) { return 1.f / (1.f + expf(-x)); }

__device__ __forceinline__ void grid_barrier_t0(unsigned int gen) {
    __threadfence();
    unsigned int prev = atomicAdd(&g_arrive, 1u);
    if (prev + 1u == gen * NBLK) {
        __threadfence();
        asm volatile("st.release.gpu.u32 [%0], %1;"
                     :: "l"(&g_release), "r"(gen) : "memory");
    } else {
        unsigned int v;
        do {
            asm volatile("ld.acquire.gpu.u32 %0, [%1];"
                         : "=r"(v) : "l"(&g_release) : "memory");
        } while (v < gen);
    }
}

__device__ __forceinline__ void fma2(unsigned long long& acc,
                                     unsigned long long a, unsigned long long b) {
    asm("fma.rn.f32x2 %0, %1, %2, %0;" : "+l"(acc) : "l"(a), "l"(b));
}
__device__ __forceinline__ float f2sum(unsigned long long acc) {
    uint32_t lo, hi;
    asm("mov.b64 {%0,%1}, %2;" : "=r"(lo), "=r"(hi) : "l"(acc));
    return __uint_as_float(lo) + __uint_as_float(hi);
}
__device__ __forceinline__ unsigned long long packf2(float a, float b) {
    unsigned long long r;
    asm("mov.b64 %0, {%1,%2};" : "=l"(r) : "f"(a), "f"(b));
    return r;
}
__device__ __forceinline__ uint32_t packbf(float a, float b) {
    __nv_bfloat162 t = __floats2bfloat162_rn(a, b);
    return *(uint32_t*)&t;
}

__device__ __forceinline__ void ldsm_x4(uint32_t& r0, uint32_t& r1, uint32_t& r2, uint32_t& r3,
                                        uint32_t addr) {
    asm volatile("ldmatrix.sync.aligned.m8n8.x4.shared.b16 {%0,%1,%2,%3}, [%4];"
                 : "=r"(r0), "=r"(r1), "=r"(r2), "=r"(r3) : "r"(addr));
}
__device__ __forceinline__ void mma_bf16(float c[4], const uint32_t a[4], const uint32_t b[2]) {
    asm volatile(
        "mma.sync.aligned.m16n8k16.row.col.f32.bf16.bf16.f32 "
        "{%0,%1,%2,%3}, {%4,%5,%6,%7}, {%8,%9}, {%0,%1,%2,%3};"
        : "+f"(c[0]), "+f"(c[1]), "+f"(c[2]), "+f"(c[3])
        : "r"(a[0]), "r"(a[1]), "r"(a[2]), "r"(a[3]), "r"(b[0]), "r"(b[1]));
}

// ---------------- fp32 -> bf16 ----------------
__global__ void f2bf_kernel(const float* __restrict__ s, __nv_bfloat16* __restrict__ d, int n) {
    int idx = (blockIdx.x * blockDim.x + threadIdx.x) * 4;
    if (idx >= n) return;
    float4 v = *(const float4*)(s + idx);
    uint2 p;
    p.x = packbf(v.x, v.y); p.y = packbf(v.z, v.w);
    *(uint2*)(d + idx) = p;
}

// ---------------- embedding ----------------
__global__ void embed_kernel(const int* __restrict__ tokens, const float* __restrict__ emb) {
    int id = blockIdx.x * blockDim.x + threadIdx.x;
    const int EV = Edim / 4;
    if (id >= MROWS * EV) return;
    int e4 = id % EV;
    int m  = id / EV;
    int b  = m & 3, t = m >> 2;
    int tok = tokens[b * Tlen + t];
    float4 v = ((const float4*)(emb + (size_t)tok * Edim))[e4];
    uint2 p; p.x = packbf(v.x, v.y); p.y = packbf(v.z, v.w);
    *(uint2*)(g_xbf + (size_t)id * 4) = p;
}

// ---------------- bf16 tensor-core GEMM (NT) — round-8 proven ----------------
__global__ __launch_bounds__(256)
void gemm_bf16_nt(const __nv_bfloat16* __restrict__ A, const __nv_bfloat16* __restrict__ B,
                  float* __restrict__ C, int M, int N, int K,
                  const float* __restrict__ bias1, const float* __restrict__ bias2,
                  int remap)
{
    __shared__ __align__(16) __nv_bfloat16 As[128 * 40];
    __shared__ __align__(16) __nv_bfloat16 Bs[128 * 40];
    const int tid  = threadIdx.x;
    const int wid  = tid >> 5, lane = tid & 31;
    const int g    = lane >> 2, tig = lane & 3;
    const int q    = lane >> 3, r = lane & 7;
    const int warp_m = (wid >> 2) * 64;
    const int warp_n = (wid & 3) * 32;
    const int row0 = blockIdx.x * 128;
    const int col0 = blockIdx.y * 128;

    const int ldr = tid >> 2;
    const int ldc = (tid & 3) * 8;

    const __nv_bfloat16* Ap0 = A + (size_t)(row0 + ldr) * K + ldc;
    const __nv_bfloat16* Ap1 = A + (size_t)(row0 + ldr + 64) * K + ldc;
    const __nv_bfloat16* Bp0 = B + (size_t)(col0 + ldr) * K + ldc;
    const __nv_bfloat16* Bp1 = B + (size_t)(col0 + ldr + 64) * K + ldc;

    const uint32_t as_base = (uint32_t)__cvta_generic_to_shared(As);
    const uint32_t bs_base = (uint32_t)__cvta_generic_to_shared(Bs);
    const uint32_t a_addr0 = as_base + (uint32_t)(((warp_m + (q & 1) * 8 + r) * 40 + (q >> 1) * 8) * 2);
    const uint32_t b_addr0 = bs_base + (uint32_t)(((warp_n + (q & 1) * 8 + r) * 40 + (q >> 1) * 8) * 2);

    float acc[16][4];
#pragma unroll
    for (int i = 0; i < 16; i++)
#pragma unroll
        for (int j = 0; j < 4; j++) acc[i][j] = 0.f;

    uint4 pa0 = *(const uint4*)Ap0;
    uint4 pa1 = *(const uint4*)Ap1;
    uint4 pb0 = *(const uint4*)Bp0;
    uint4 pb1 = *(const uint4*)Bp1;

    for (int kb = 0; kb < K; kb += 32) {
        *(uint4*)&As[ldr * 40 + ldc]        = pa0;
        *(uint4*)&As[(ldr + 64) * 40 + ldc] = pa1;
        *(uint4*)&Bs[ldr * 40 + ldc]        = pb0;
        *(uint4*)&Bs[(ldr + 64) * 40 + ldc] = pb1;
        __syncthreads();

        if (kb + 32 < K) {
            pa0 = *(const uint4*)(Ap0 + kb + 32);
            pa1 = *(const uint4*)(Ap1 + kb + 32);
            pb0 = *(const uint4*)(Bp0 + kb + 32);
            pb1 = *(const uint4*)(Bp1 + kb + 32);
        }

#pragma unroll
        for (int ks = 0; ks < 2; ks++) {
            uint32_t af[4][4], bf[4][2];
#pragma unroll
            for (int mt = 0; mt < 4; mt++)
                ldsm_x4(af[mt][0], af[mt][1], af[mt][2], af[mt][3],
                        a_addr0 + (uint32_t)((mt * 16 * 40 + ks * 16) * 2));
#pragma unroll
            for (int bt = 0; bt < 2; bt++) {
                uint32_t m0, m1, m2, m3;
                ldsm_x4(m0, m1, m2, m3,
                        b_addr0 + (uint32_t)((bt * 16 * 40 + ks * 16) * 2));
                bf[bt * 2 + 0][0] = m0; bf[bt * 2 + 1][0] = m1;
                bf[bt * 2 + 0][1] = m2; bf[bt * 2 + 1][1] = m3;
            }
#pragma unroll
            for (int mt = 0; mt < 4; mt++)
#pragma unroll
                for (int nt = 0; nt < 4; nt++)
                    mma_bf16(acc[mt * 4 + nt], af[mt], bf[nt]);
        }
        __syncthreads();
    }

#pragma unroll
    for (int mt = 0; mt < 4; mt++) {
        int m0 = row0 + warp_m + mt * 16 + g;
        int m1 = m0 + 8;
        int r0 = remap ? ((m0 & 3) * Tlen + (m0 >> 2)) : m0;
        int r1 = remap ? ((m1 & 3) * Tlen + (m1 >> 2)) : m1;
#pragma unroll
        for (int nt = 0; nt < 4; nt++) {
            int n = col0 + warp_n + nt * 8 + tig * 2;
            float bv0 = 0.f, bv1 = 0.f;
            if (bias1) { bv0 += bias1[n]; bv1 += bias1[n + 1]; }
            if (bias2) { bv0 += bias2[n]; bv1 += bias2[n + 1]; }
            float* c = acc[mt * 4 + nt];
            *(float2*)&C[(size_t)r0 * N + n] = make_float2(c[0] + bv0, c[1] + bv1);
            *(float2*)&C[(size_t)r1 * N + n] = make_float2(c[2] + bv0, c[3] + bv1);
        }
    }
}

// ---------------- persistent LSTM layer: register-resident Whh,
// fp32 h staging, f32x2 FMA, gate prefetch at loop top ----------------
__global__ void __launch_bounds__(256, 1)
lstm_layer(const float* __restrict__ gih,          // [T,B,4E] fp32 gates (+bias)
           const float* __restrict__ Whh,          // [4E,E] fp32
           __nv_bfloat16* __restrict__ hbf,        // [T+1,B,E] bf16
           unsigned int gen_base)                  // barrier generation offset
{
    __shared__ __align__(16) float hs[4 * Edim];   // fp32 h_prev (16KB)
    __shared__ float garr[128];
    __shared__ float cs[32];

    const int blk  = blockIdx.x;
    const int e0   = blk * 8;
    const int tid  = threadIdx.x;
    const int warp = tid >> 5;
    const int lane = tid & 31;

    unsigned long long wreg[4][16];
#pragma unroll
    for (int rr = 0; rr < 4; rr++) {
        int r = warp * 4 + rr, g = r >> 3, j = r & 7;
        const float* src = Whh + (size_t)(g * Edim + e0 + j) * Edim;
#pragma unroll
        for (int jj = 0; jj < 16; jj++) {
            int kp = lane + 32 * jj;
            float2 v = *(const float2*)&src[kp * 2];
            wreg[rr][jj] = packf2(v.x, v.y);
        }
    }
    if (tid < 32) cs[tid] = 0.f;
    __syncthreads();

    // pointwise thread constants
    const int pb = tid >> 3, pj = tid & 7, pe = e0 + pj;

    for (int t = 0; t < Tlen; t++) {
        // PREFETCH this step's 4 gate values (independent of h) — hide L2
        // latency under staging + dot instead of stalling after the dot.
        float pgi = 0.f, pgf = 0.f, pgG = 0.f, pgo = 0.f;
        if (tid < 32) {
            const float* gb = gih + ((size_t)t * Bsz + pb) * GDIM;
            pgi = __ldg(&gb[pe]);
            pgf = __ldg(&gb[Edim + pe]);
            pgG = __ldg(&gb[2 * Edim + pe]);
            pgo = __ldg(&gb[3 * Edim + pe]);
        }

        // stage h_prev as fp32
        if (t == 0) {
            for (int i = tid; i < 4 * Edim; i += 256) hs[i] = 0.f;
        } else {
            const uint4* hp = (const uint4*)(hbf + (size_t)t * (Bsz * Edim));
#pragma unroll
            for (int i = tid; i < 512; i += 256) {
                uint4 p = hp[i];
                float* d = hs + i * 8;
                d[0] = __uint_as_float(p.x << 16);
                d[1] = __uint_as_float(p.x & 0xFFFF0000u);
                d[2] = __uint_as_float(p.y << 16);
                d[3] = __uint_as_float(p.y & 0xFFFF0000u);
                d[4] = __uint_as_float(p.z << 16);
                d[5] = __uint_as_float(p.z & 0xFFFF0000u);
                d[6] = __uint_as_float(p.w << 16);
                d[7] = __uint_as_float(p.w & 0xFFFF0000u);
            }
        }
        __syncthreads();

        unsigned long long acc[16];
#pragma unroll
        for (int i = 0; i < 16; i++) acc[i] = 0ull;

#pragma unroll
        for (int jj = 0; jj < 16; jj++) {
            int kp = lane + 32 * jj;
            unsigned long long H0 = *(const unsigned long long*)&hs[kp * 2];
            unsigned long long H1 = *(const unsigned long long*)&hs[Edim + kp * 2];
            unsigned long long H2 = *(const unsigned long long*)&hs[2 * Edim + kp * 2];
            unsigned long long H3 = *(const unsigned long long*)&hs[3 * Edim + kp * 2];
            fma2(acc[ 0], wreg[0][jj], H0); fma2(acc[ 1], wreg[0][jj], H1);
            fma2(acc[ 2], wreg[0][jj], H2); fma2(acc[ 3], wreg[0][jj], H3);
            fma2(acc[ 4], wreg[1][jj], H0); fma2(acc[ 5], wreg[1][jj], H1);
            fma2(acc[ 6], wreg[1][jj], H2); fma2(acc[ 7], wreg[1][jj], H3);
            fma2(acc[ 8], wreg[2][jj], H0); fma2(acc[ 9], wreg[2][jj], H1);
            fma2(acc[10], wreg[2][jj], H2); fma2(acc[11], wreg[2][jj], H3);
            fma2(acc[12], wreg[3][jj], H0); fma2(acc[13], wreg[3][jj], H1);
            fma2(acc[14], wreg[3][jj], H2); fma2(acc[15], wreg[3][jj], H3);
        }

        float a[16];
#pragma unroll
        for (int i = 0; i < 16; i++) a[i] = f2sum(acc[i]);
#pragma unroll
        for (int off = 16; off; off >>= 1)
#pragma unroll
            for (int i = 0; i < 16; i++)
                a[i] += __shfl_down_sync(~0u, a[i], off);

        if (lane == 0) {
#pragma unroll
            for (int rr = 0; rr < 4; rr++) {
                int r = warp * 4 + rr, g = r >> 3, j = r & 7;
#pragma unroll
                for (int b = 0; b < 4; b++)
                    garr[(g * 4 + b) * 8 + j] = a[rr * 4 + b];
            }
        }
        __syncthreads();

        if (tid < 32) {
            float gi = garr[(0 * 4 + pb) * 8 + pj] + pgi;
            float gf = garr[(1 * 4 + pb) * 8 + pj] + pgf;
            float gG = garr[(2 * 4 + pb) * 8 + pj] + pgG;
            float go = garr[(3 * 4 + pb) * 8 + pj] + pgo;
            float c = sigm(gf) * cs[tid] + sigm(gi) * tanh_acc(gG);
            cs[tid] = c;
            float hv = sigm(go) * tanh_acc(c);
            hbf[(size_t)(t + 1) * (Bsz * Edim) + pb * Edim + pe] = __float2bfloat16(hv);
        }
        __syncthreads();

        if (tid == 0) grid_barrier_t0(gen_base + (unsigned int)(t + 1));
        __syncthreads();
    }
}

// ---------------- post-processing (round-12 proven) ----------------
__global__ void postprocess(float* __restrict__ out) {
    const int r = blockIdx.x;
    const int t_idx = r & (Tlen - 1);
    float* z = out + (size_t)r * Vdim;
    const int tid = threadIdx.x;

    __shared__ float redm[256];
    __shared__ float reds[256];
    __shared__ float sh_shift, sh_eos;

    float m = -3.402823466e38f, s = 0.f;
    const float4* z4 = (const float4*)z;
    for (int i = tid; i < 7999; i += 256) {
        float4 v = z4[i];
        float mv = fmaxf(fmaxf(v.x, v.y), fmaxf(v.z, v.w));
        float m2 = fmaxf(m, mv);
        s = s * expf(m - m2)
          + expf(v.x - m2) + expf(v.y - m2) + expf(v.z - m2) + expf(v.w - m2);
        m = m2;
    }
    if (tid < 3) {
        float x = z[31996 + tid];
        float m2 = fmaxf(m, x);
        s = s * expf(m - m2) + expf(x - m2);
        m = m2;
    }
    redm[tid] = m; reds[tid] = s;
    __syncthreads();
#pragma unroll
    for (int st = 128; st; st >>= 1) {
        if (tid < st) {
            float mo = redm[tid], so = reds[tid];
            float mn = redm[tid + st], sn = reds[tid + st];
            float mm = fmaxf(mo, mn);
            redm[tid] = mm;
            reds[tid] = so * expf(mo - mm) + sn * expf(mn - mm);
        }
        __syncthreads();
    }

    if (tid == 0) {
        double lse = (double)redm[0] + log((double)reds[0]);
        double e   = (double)z[Vdim - 1];
        double lsn = (-e < 0 ? -e : 0.0) - log1p(exp(-fabs(e)));
        double lsp = ( e < 0 ?  e : 0.0) - log1p(exp(-fabs(e)));
        double log_lb = (double)(t_idx + 1) * LOGB;
        double C1 = log_lb + lsn;
        double log_lb_eos = log(-expm1(log_lb)) + lsn;
        double d = log_lb_eos - lsp;
        double logsig_d = (d < 0 ? d : 0.0) - log1p(exp(-fabs(d)));
        double lpe = log_lb_eos - logsig_d;
        double m2 = fmax(C1, lpe);
        double Z  = m2 + log1p(exp(fmin(C1, lpe) - m2));
        sh_shift = (float)(C1 - lse - Z);
        sh_eos   = (float)(lpe - Z);
    }
    __syncthreads();

    float shift = sh_shift;
    float4* zw = (float4*)z;
    for (int i = tid; i < 7999; i += 256) {
        float4 v = zw[i];
        v.x += shift; v.y += shift; v.z += shift; v.w += shift;
        zw[i] = v;
    }
    if (tid < 3) z[31996 + tid] += shift;
    if (tid == 0) z[Vdim - 1] = sh_eos;
}

// ---------------- launcher ----------------
extern "C" void kernel_launch(void* const* d_in, const int* in_sizes, int n_in,
                              void* d_out, int out_size)
{
    (void)in_sizes; (void)n_in; (void)out_size;
    // 0:tokens 1:emb 2:Wproj 3:Wih0 4:Whh0 5:bih0 6:bhh0 7:Wih1 8:Whh1 9:bih1 10:bhh1
    const int*   tokens = (const int*)  d_in[0];
    const float* emb    = (const float*)d_in[1];
    const float* Wproj  = (const float*)d_in[2];
    const float* Wih0   = (const float*)d_in[3];
    const float* Whh0   = (const float*)d_in[4];
    const float* bih0   = (const float*)d_in[5];
    const float* bhh0   = (const float*)d_in[6];
    const float* Wih1   = (const float*)d_in[7];
    const float* Whh1   = (const float*)d_in[8];
    const float* bih1   = (const float*)d_in[9];
    const float* bhh1   = (const float*)d_in[10];
    float* out = (float*)d_out;

    __nv_bfloat16 *pxbf, *ph0bf, *ph1bf, *pw0, *pw1, *pwp;
    float *pg;
    cudaGetSymbolAddress((void**)&pxbf,  g_xbf);
    cudaGetSymbolAddress((void**)&pg,    g_gates);
    cudaGetSymbolAddress((void**)&ph0bf, g_h0bf);
    cudaGetSymbolAddress((void**)&ph1bf, g_h1bf);
    cudaGetSymbolAddress((void**)&pw0,   g_wih0bf);
    cudaGetSymbolAddress((void**)&pw1,   g_wih1bf);
    cudaGetSymbolAddress((void**)&pwp,   g_wprojbf);

    // 0. weight conversions + barrier reset (single reset covers both layers
    //    via monotonic generations)
    bar_reset<<<1, 1>>>();
    f2bf_kernel<<<GDIM * Edim / 1024, 256>>>(Wih0, pw0, GDIM * Edim);
    f2bf_kernel<<<GDIM * Edim / 1024, 256>>>(Wih1, pw1, GDIM * Edim);
    f2bf_kernel<<<Vdim * (Edim / 1024), 256>>>(Wproj, pwp, Vdim * Edim);

    // 1. embedding
    embed_kernel<<<(MROWS * Edim / 4 + 255) / 256, 256>>>(tokens, emb);

    // 2. layer-0 input gates (bf16 tensor cores)
    dim3 gg(MROWS / 128, GDIM / 128);
    gemm_bf16_nt<<<gg, 256>>>(pxbf, pw0, pg, MROWS, GDIM, Edim, bih0, bhh0, 0);

    // 3. layer-0 recurrence (generations 1..512)
    lstm_layer<<<NBLK, 256>>>(pg, Whh0, ph0bf, 0u);

    // 4. layer-1 input gates
    gemm_bf16_nt<<<gg, 256>>>(ph0bf + Bsz * Edim, pw1, pg, MROWS, GDIM, Edim, bih1, bhh1, 0);

    // 5. layer-1 recurrence (generations 513..1024)
    lstm_layer<<<NBLK, 256>>>(pg, Whh1, ph1bf, (unsigned int)Tlen);

    // 6. projection -> d_out with [B,T] remap
    dim3 gp(MROWS / 128, Vdim / 128);
    gemm_bf16_nt<<<gp, 256>>>(ph1bf + Bsz * Edim, pwp, out, MROWS, Vdim, Edim,
                              nullptr, nullptr, 1);

    // 7. post-processing
    postprocess<<<MROWS, 256>>>(out);
}

// round 16
// speedup vs baseline: 1.4995x; 1.0159x over previous
#include <cuda_runtime.h>
#include <cuda_bf16.h>
#include <math.h>
#include <stdint.h>

#define Bsz  4
#define Tlen 512
#define Edim 1024
#define Vdim 32000
#define GDIM (4*Edim)           // 4096
#define MROWS (Tlen*Bsz)        // 2048
#define NBLK 128
#define LOGB (-1.0005003335835335e-3)

// ---------------- scratch ----------------
static __device__ __align__(16) __nv_bfloat16 g_xbf [MROWS * Edim];
static __device__ __align__(16) float g_gates[MROWS * GDIM];
static __device__ __align__(16) __nv_bfloat16 g_h0bf[(Tlen+1) * Bsz*Edim];
static __device__ __align__(16) __nv_bfloat16 g_h1bf[(Tlen+1) * Bsz*Edim];
static __device__ __align__(16) __nv_bfloat16 g_wih0bf[GDIM * Edim];
static __device__ __align__(16) __nv_bfloat16 g_wih1bf[GDIM * Edim];
static __device__ __align__(16) __nv_bfloat16 g_wprojbf[(size_t)Vdim * Edim];

// grid-barrier (proven)
static __device__ unsigned int g_arrive;
static __device__ unsigned int g_release;
__global__ void bar_reset() { g_arrive = 0; g_release = 0; }

// ---------------- helpers ----------------
__device__ __forceinline__ float tanh_acc(float x) {
    float ax = fabsf(x);
    float t  = expf(-2.f * ax);
    float r  = (1.f - t) / (1.f + t);
    return copysignf(r, x);
}
__device__ __forceinline__ float sigm(float x) { return 1.f / (1.f + expf(-x)); }

__device__ __forceinline__ void grid_barrier_t0(unsigned int gen) {
    __threadfence();
    unsigned int prev = atomicAdd(&g_arrive, 1u);
    if (prev + 1u == gen * NBLK) {
        __threadfence();
        asm volatile("st.release.gpu.u32 [%0], %1;"
                     :: "l"(&g_release), "r"(gen) : "memory");
    } else {
        unsigned int v;
        do {
            asm volatile("ld.acquire.gpu.u32 %0, [%1];"
                         : "=r"(v) : "l"(&g_release) : "memory");
        } while (v < gen);
    }
}

__device__ __forceinline__ void fma2(unsigned long long& acc,
                                     unsigned long long a, unsigned long long b) {
    asm("fma.rn.f32x2 %0, %1, %2, %0;" : "+l"(acc) : "l"(a), "l"(b));
}
__device__ __forceinline__ float f2sum(unsigned long long acc) {
    uint32_t lo, hi;
    asm("mov.b64 {%0,%1}, %2;" : "=r"(lo), "=r"(hi) : "l"(acc));
    return __uint_as_float(lo) + __uint_as_float(hi);
}
__device__ __forceinline__ unsigned long long packf2(float a, float b) {
    unsigned long long r;
    asm("mov.b64 %0, {%1,%2};" : "=l"(r) : "f"(a), "f"(b));
    return r;
}
__device__ __forceinline__ uint32_t packbf(float a, float b) {
    __nv_bfloat162 t = __floats2bfloat162_rn(a, b);
    return *(uint32_t*)&t;
}

__device__ __forceinline__ void ldsm_x4(uint32_t& r0, uint32_t& r1, uint32_t& r2, uint32_t& r3,
                                        uint32_t addr) {
    asm volatile("ldmatrix.sync.aligned.m8n8.x4.shared.b16 {%0,%1,%2,%3}, [%4];"
                 : "=r"(r0), "=r"(r1), "=r"(r2), "=r"(r3) : "r"(addr));
}
__device__ __forceinline__ void mma_bf16(float c[4], const uint32_t a[4], const uint32_t b[2]) {
    asm volatile(
        "mma.sync.aligned.m16n8k16.row.col.f32.bf16.bf16.f32 "
        "{%0,%1,%2,%3}, {%4,%5,%6,%7}, {%8,%9}, {%0,%1,%2,%3};"
        : "+f"(c[0]), "+f"(c[1]), "+f"(c[2]), "+f"(c[3])
        : "r"(a[0]), "r"(a[1]), "r"(a[2]), "r"(a[3]), "r"(b[0]), "r"(b[1]));
}

__device__ __forceinline__ void cp_async16(uint32_t dst, const void* src) {
    asm volatile("cp.async.ca.shared.global [%0], [%1], 16;"
                 :: "r"(dst), "l"(src) : "memory");
}
__device__ __forceinline__ void cp_commit() {
    asm volatile("cp.async.commit_group;" ::: "memory");
}
__device__ __forceinline__ void cp_wait0() {
    asm volatile("cp.async.wait_group 0;" ::: "memory");
}

// ---------------- fp32 -> bf16 ----------------
__global__ void f2bf_kernel(const float* __restrict__ s, __nv_bfloat16* __restrict__ d, int n) {
    int idx = (blockIdx.x * blockDim.x + threadIdx.x) * 4;
    if (idx >= n) return;
    float4 v = *(const float4*)(s + idx);
    uint2 p;
    p.x = packbf(v.x, v.y); p.y = packbf(v.z, v.w);
    *(uint2*)(d + idx) = p;
}

// ---------------- embedding ----------------
__global__ void embed_kernel(const int* __restrict__ tokens, const float* __restrict__ emb) {
    int id = blockIdx.x * blockDim.x + threadIdx.x;
    const int EV = Edim / 4;
    if (id >= MROWS * EV) return;
    int e4 = id % EV;
    int m  = id / EV;
    int b  = m & 3, t = m >> 2;
    int tok = tokens[b * Tlen + t];
    float4 v = ((const float4*)(emb + (size_t)tok * Edim))[e4];
    uint2 p; p.x = packbf(v.x, v.y); p.y = packbf(v.z, v.w);
    *(uint2*)(g_xbf + (size_t)id * 4) = p;
}

// ---------------- bf16 tensor-core GEMM (NT), cp.async double-buffered ----------------
__global__ __launch_bounds__(256)
void gemm_bf16_nt(const __nv_bfloat16* __restrict__ A, const __nv_bfloat16* __restrict__ B,
                  float* __restrict__ C, int M, int N, int K,
                  const float* __restrict__ bias1, const float* __restrict__ bias2,
                  int remap)
{
    __shared__ __align__(16) __nv_bfloat16 As[2][128 * 40];
    __shared__ __align__(16) __nv_bfloat16 Bs[2][128 * 40];
    const int tid  = threadIdx.x;
    const int wid  = tid >> 5, lane = tid & 31;
    const int g    = lane >> 2, tig = lane & 3;
    const int q    = lane >> 3, r = lane & 7;
    const int warp_m = (wid >> 2) * 64;
    const int warp_n = (wid & 3) * 32;
    const int row0 = blockIdx.x * 128;
    const int col0 = blockIdx.y * 128;

    const int ldr = tid >> 2;
    const int ldc = (tid & 3) * 8;

    const __nv_bfloat16* Ap0 = A + (size_t)(row0 + ldr) * K + ldc;
    const __nv_bfloat16* Ap1 = A + (size_t)(row0 + ldr + 64) * K + ldc;
    const __nv_bfloat16* Bp0 = B + (size_t)(col0 + ldr) * K + ldc;
    const __nv_bfloat16* Bp1 = B + (size_t)(col0 + ldr + 64) * K + ldc;

    uint32_t sa[2], sb[2];
    sa[0] = (uint32_t)__cvta_generic_to_shared(As[0]);
    sa[1] = (uint32_t)__cvta_generic_to_shared(As[1]);
    sb[0] = (uint32_t)__cvta_generic_to_shared(Bs[0]);
    sb[1] = (uint32_t)__cvta_generic_to_shared(Bs[1]);
    const uint32_t st_off0 = (uint32_t)((ldr * 40 + ldc) * 2);
    const uint32_t st_off1 = (uint32_t)(((ldr + 64) * 40 + ldc) * 2);
    const uint32_t frag_a  = (uint32_t)(((warp_m + (q & 1) * 8 + r) * 40 + (q >> 1) * 8) * 2);
    const uint32_t frag_b  = (uint32_t)(((warp_n + (q & 1) * 8 + r) * 40 + (q >> 1) * 8) * 2);

    float acc[16][4];
#pragma unroll
    for (int i = 0; i < 16; i++)
#pragma unroll
        for (int j = 0; j < 4; j++) acc[i][j] = 0.f;

    const int nslab = K / 32;

    // prologue: async-load slab 0 into buffer 0
    cp_async16(sa[0] + st_off0, Ap0);
    cp_async16(sa[0] + st_off1, Ap1);
    cp_async16(sb[0] + st_off0, Bp0);
    cp_async16(sb[0] + st_off1, Bp1);
    cp_commit();

    for (int s = 0; s < nslab; s++) {
        const int bq = s & 1;
        cp_wait0();              // slab s landed (its copy overlapped compute of s-1)
        __syncthreads();         // all warps: data visible, buf bq^1 free

        if (s + 1 < nslab) {     // issue slab s+1 into the other buffer
            int off = (s + 1) * 32;
            cp_async16(sa[bq ^ 1] + st_off0, Ap0 + off);
            cp_async16(sa[bq ^ 1] + st_off1, Ap1 + off);
            cp_async16(sb[bq ^ 1] + st_off0, Bp0 + off);
            cp_async16(sb[bq ^ 1] + st_off1, Bp1 + off);
            cp_commit();
        }

        const uint32_t a_addr0 = sa[bq] + frag_a;
        const uint32_t b_addr0 = sb[bq] + frag_b;
#pragma unroll
        for (int ks = 0; ks < 2; ks++) {
            uint32_t af[4][4], bf[4][2];
#pragma unroll
            for (int mt = 0; mt < 4; mt++)
                ldsm_x4(af[mt][0], af[mt][1], af[mt][2], af[mt][3],
                        a_addr0 + (uint32_t)((mt * 16 * 40 + ks * 16) * 2));
#pragma unroll
            for (int bt = 0; bt < 2; bt++) {
                uint32_t m0, m1, m2, m3;
                ldsm_x4(m0, m1, m2, m3,
                        b_addr0 + (uint32_t)((bt * 16 * 40 + ks * 16) * 2));
                bf[bt * 2 + 0][0] = m0; bf[bt * 2 + 1][0] = m1;
                bf[bt * 2 + 0][1] = m2; bf[bt * 2 + 1][1] = m3;
            }
#pragma unroll
            for (int mt = 0; mt < 4; mt++)
#pragma unroll
                for (int nt = 0; nt < 4; nt++)
                    mma_bf16(acc[mt * 4 + nt], af[mt], bf[nt]);
        }
    }

#pragma unroll
    for (int mt = 0; mt < 4; mt++) {
        int m0 = row0 + warp_m + mt * 16 + g;
        int m1 = m0 + 8;
        int r0 = remap ? ((m0 & 3) * Tlen + (m0 >> 2)) : m0;
        int r1 = remap ? ((m1 & 3) * Tlen + (m1 >> 2)) : m1;
#pragma unroll
        for (int nt = 0; nt < 4; nt++) {
            int n = col0 + warp_n + nt * 8 + tig * 2;
            float bv0 = 0.f, bv1 = 0.f;
            if (bias1) { bv0 += bias1[n]; bv1 += bias1[n + 1]; }
            if (bias2) { bv0 += bias2[n]; bv1 += bias2[n + 1]; }
            float* c = acc[mt * 4 + nt];
            *(float2*)&C[(size_t)r0 * N + n] = make_float2(c[0] + bv0, c[1] + bv1);
            *(float2*)&C[(size_t)r1 * N + n] = make_float2(c[2] + bv0, c[3] + bv1);
        }
    }
}

// ---------------- persistent LSTM layer: register-resident Whh, fp32 h staging,
// f32x2 FMA, gate prefetch, early warp-0 barrier arrive ----------------
__global__ void __launch_bounds__(256, 1)
lstm_layer(const float* __restrict__ gih,          // [T,B,4E] fp32 gates (+bias)
           const float* __restrict__ Whh,          // [4E,E] fp32
           __nv_bfloat16* __restrict__ hbf,        // [T+1,B,E] bf16
           unsigned int gen_base)
{
    __shared__ __align__(16) float hs[4 * Edim];
    __shared__ float garr[128];
    __shared__ float cs[32];

    const int blk  = blockIdx.x;
    const int e0   = blk * 8;
    const int tid  = threadIdx.x;
    const int warp = tid >> 5;
    const int lane = tid & 31;

    unsigned long long wreg[4][16];
#pragma unroll
    for (int rr = 0; rr < 4; rr++) {
        int r = warp * 4 + rr, g = r >> 3, j = r & 7;
        const float* src = Whh + (size_t)(g * Edim + e0 + j) * Edim;
#pragma unroll
        for (int jj = 0; jj < 16; jj++) {
            int kp = lane + 32 * jj;
            float2 v = *(const float2*)&src[kp * 2];
            wreg[rr][jj] = packf2(v.x, v.y);
        }
    }
    if (tid < 32) cs[tid] = 0.f;
    __syncthreads();

    const int pb = tid >> 3, pj = tid & 7, pe = e0 + pj;

    for (int t = 0; t < Tlen; t++) {
        // prefetch this step's gate values (hide L2 latency under staging+dot)
        float pgi = 0.f, pgf = 0.f, pgG = 0.f, pgo = 0.f;
        if (tid < 32) {
            const float* gb = gih + ((size_t)t * Bsz + pb) * GDIM;
            pgi = __ldg(&gb[pe]);
            pgf = __ldg(&gb[Edim + pe]);
            pgG = __ldg(&gb[2 * Edim + pe]);
            pgo = __ldg(&gb[3 * Edim + pe]);
        }

        if (t == 0) {
            for (int i = tid; i < 4 * Edim; i += 256) hs[i] = 0.f;
        } else {
            const uint4* hp = (const uint4*)(hbf + (size_t)t * (Bsz * Edim));
#pragma unroll
            for (int i = tid; i < 512; i += 256) {
                uint4 p = hp[i];
                float* d = hs + i * 8;
                d[0] = __uint_as_float(p.x << 16);
                d[1] = __uint_as_float(p.x & 0xFFFF0000u);
                d[2] = __uint_as_float(p.y << 16);
                d[3] = __uint_as_float(p.y & 0xFFFF0000u);
                d[4] = __uint_as_float(p.z << 16);
                d[5] = __uint_as_float(p.z & 0xFFFF0000u);
                d[6] = __uint_as_float(p.w << 16);
                d[7] = __uint_as_float(p.w & 0xFFFF0000u);
            }
        }
        __syncthreads();

        unsigned long long acc[16];
#pragma unroll
        for (int i = 0; i < 16; i++) acc[i] = 0ull;

#pragma unroll
        for (int jj = 0; jj < 16; jj++) {
            int kp = lane + 32 * jj;
            unsigned long long H0 = *(const unsigned long long*)&hs[kp * 2];
            unsigned long long H1 = *(const unsigned long long*)&hs[Edim + kp * 2];
            unsigned long long H2 = *(const unsigned long long*)&hs[2 * Edim + kp * 2];
            unsigned long long H3 = *(const unsigned long long*)&hs[3 * Edim + kp * 2];
            fma2(acc[ 0], wreg[0][jj], H0); fma2(acc[ 1], wreg[0][jj], H1);
            fma2(acc[ 2], wreg[0][jj], H2); fma2(acc[ 3], wreg[0][jj], H3);
            fma2(acc[ 4], wreg[1][jj], H0); fma2(acc[ 5], wreg[1][jj], H1);
            fma2(acc[ 6], wreg[1][jj], H2); fma2(acc[ 7], wreg[1][jj], H3);
            fma2(acc[ 8], wreg[2][jj], H0); fma2(acc[ 9], wreg[2][jj], H1);
            fma2(acc[10], wreg[2][jj], H2); fma2(acc[11], wreg[2][jj], H3);
            fma2(acc[12], wreg[3][jj], H0); fma2(acc[13], wreg[3][jj], H1);
            fma2(acc[14], wreg[3][jj], H2); fma2(acc[15], wreg[3][jj], H3);
        }

        float a[16];
#pragma unroll
        for (int i = 0; i < 16; i++) a[i] = f2sum(acc[i]);
#pragma unroll
        for (int off = 16; off; off >>= 1)
#pragma unroll
            for (int i = 0; i < 16; i++)
                a[i] += __shfl_down_sync(~0u, a[i], off);

        if (lane == 0) {
#pragma unroll
            for (int rr = 0; rr < 4; rr++) {
                int r = warp * 4 + rr, g = r >> 3, j = r & 7;
#pragma unroll
                for (int b = 0; b < 4; b++)
                    garr[(g * 4 + b) * 8 + j] = a[rr * 4 + b];
            }
        }
        __syncthreads();

        // warp 0: pointwise + h store + EARLY barrier arrive (no block sync first —
        // all h stores for this block are made by warp 0; syncwarp + fence covers them)
        if (tid < 32) {
            float gi = garr[(0 * 4 + pb) * 8 + pj] + pgi;
            float gf = garr[(1 * 4 + pb) * 8 + pj] + pgf;
            float gG = garr[(2 * 4 + pb) * 8 + pj] + pgG;
            float go = garr[(3 * 4 + pb) * 8 + pj] + pgo;
            float c = sigm(gf) * cs[tid] + sigm(gi) * tanh_acc(gG);
            cs[tid] = c;
            float hv = sigm(go) * tanh_acc(c);
            hbf[(size_t)(t + 1) * (Bsz * Edim) + pb * Edim + pe] = __float2bfloat16(hv);
            __syncwarp();
            if (tid == 0) grid_barrier_t0(gen_base + (unsigned int)(t + 1));
        }
        __syncthreads();   // all warps wait for warp 0's release observation
    }
}

// ---------------- post-processing (proven) ----------------
__global__ void postprocess(float* __restrict__ out) {
    const int r = blockIdx.x;
    const int t_idx = r & (Tlen - 1);
    float* z = out + (size_t)r * Vdim;
    const int tid = threadIdx.x;

    __shared__ float redm[256];
    __shared__ float reds[256];
    __shared__ float sh_shift, sh_eos;

    float m = -3.402823466e38f, s = 0.f;
    const float4* z4 = (const float4*)z;
    for (int i = tid; i < 7999; i += 256) {
        float4 v = z4[i];
        float mv = fmaxf(fmaxf(v.x, v.y), fmaxf(v.z, v.w));
        float m2 = fmaxf(m, mv);
        s = s * expf(m - m2)
          + expf(v.x - m2) + expf(v.y - m2) + expf(v.z - m2) + expf(v.w - m2);
        m = m2;
    }
    if (tid < 3) {
        float x = z[31996 + tid];
        float m2 = fmaxf(m, x);
        s = s * expf(m - m2) + expf(x - m2);
        m = m2;
    }
    redm[tid] = m; reds[tid] = s;
    __syncthreads();
#pragma unroll
    for (int st = 128; st; st >>= 1) {
        if (tid < st) {
            float mo = redm[tid], so = reds[tid];
            float mn = redm[tid + st], sn = reds[tid + st];
            float mm = fmaxf(mo, mn);
            redm[tid] = mm;
            reds[tid] = so * expf(mo - mm) + sn * expf(mn - mm);
        }
        __syncthreads();
    }

    if (tid == 0) {
        double lse = (double)redm[0] + log((double)reds[0]);
        double e   = (double)z[Vdim - 1];
        double lsn = (-e < 0 ? -e : 0.0) - log1p(exp(-fabs(e)));
        double lsp = ( e < 0 ?  e : 0.0) - log1p(exp(-fabs(e)));
        double log_lb = (double)(t_idx + 1) * LOGB;
        double C1 = log_lb + lsn;
        double log_lb_eos = log(-expm1(log_lb)) + lsn;
        double d = log_lb_eos - lsp;
        double logsig_d = (d < 0 ? d : 0.0) - log1p(exp(-fabs(d)));
        double lpe = log_lb_eos - logsig_d;
        double m2 = fmax(C1, lpe);
        double Z  = m2 + log1p(exp(fmin(C1, lpe) - m2));
        sh_shift = (float)(C1 - lse - Z);
        sh_eos   = (float)(lpe - Z);
    }
    __syncthreads();

    float shift = sh_shift;
    float4* zw = (float4*)z;
    for (int i = tid; i < 7999; i += 256) {
        float4 v = zw[i];
        v.x += shift; v.y += shift; v.z += shift; v.w += shift;
        zw[i] = v;
    }
    if (tid < 3) z[31996 + tid] += shift;
    if (tid == 0) z[Vdim - 1] = sh_eos;
}

// ---------------- launcher ----------------
extern "C" void kernel_launch(void* const* d_in, const int* in_sizes, int n_in,
                              void* d_out, int out_size)
{
    (void)in_sizes; (void)n_in; (void)out_size;
    // 0:tokens 1:emb 2:Wproj 3:Wih0 4:Whh0 5:bih0 6:bhh0 7:Wih1 8:Whh1 9:bih1 10:bhh1
    const int*   tokens = (const int*)  d_in[0];
    const float* emb    = (const float*)d_in[1];
    const float* Wproj  = (const float*)d_in[2];
    const float* Wih0   = (const float*)d_in[3];
    const float* Whh0   = (const float*)d_in[4];
    const float* bih0   = (const float*)d_in[5];
    const float* bhh0   = (const float*)d_in[6];
    const float* Wih1   = (const float*)d_in[7];
    const float* Whh1   = (const float*)d_in[8];
    const float* bih1   = (const float*)d_in[9];
    const float* bhh1   = (const float*)d_in[10];
    float* out = (float*)d_out;

    __nv_bfloat16 *pxbf, *ph0bf, *ph1bf, *pw0, *pw1, *pwp;
    float *pg;
    cudaGetSymbolAddress((void**)&pxbf,  g_xbf);
    cudaGetSymbolAddress((void**)&pg,    g_gates);
    cudaGetSymbolAddress((void**)&ph0bf, g_h0bf);
    cudaGetSymbolAddress((void**)&ph1bf, g_h1bf);
    cudaGetSymbolAddress((void**)&pw0,   g_wih0bf);
    cudaGetSymbolAddress((void**)&pw1,   g_wih1bf);
    cudaGetSymbolAddress((void**)&pwp,   g_wprojbf);

    // 0. barrier reset + weight conversions
    bar_reset<<<1, 1>>>();
    f2bf_kernel<<<GDIM * Edim / 1024, 256>>>(Wih0, pw0, GDIM * Edim);
    f2bf_kernel<<<GDIM * Edim / 1024, 256>>>(Wih1, pw1, GDIM * Edim);
    f2bf_kernel<<<Vdim * (Edim / 1024), 256>>>(Wproj, pwp, Vdim * Edim);

    // 1. embedding
    embed_kernel<<<(MROWS * Edim / 4 + 255) / 256, 256>>>(tokens, emb);

    // 2. layer-0 input gates
    dim3 gg(MROWS / 128, GDIM / 128);
    gemm_bf16_nt<<<gg, 256>>>(pxbf, pw0, pg, MROWS, GDIM, Edim, bih0, bhh0, 0);

    // 3. layer-0 recurrence (generations 1..512)
    lstm_layer<<<NBLK, 256>>>(pg, Whh0, ph0bf, 0u);

    // 4. layer-1 input gates
    gemm_bf16_nt<<<gg, 256>>>(ph0bf + Bsz * Edim, pw1, pg, MROWS, GDIM, Edim, bih1, bhh1, 0);

    // 5. layer-1 recurrence (generations 513..1024)
    lstm_layer<<<NBLK, 256>>>(pg, Whh1, ph1bf, (unsigned int)Tlen);

    // 6. projection -> d_out with [B,T] remap
    dim3 gp(MROWS / 128, Vdim / 128);
    gemm_bf16_nt<<<gp, 256>>>(ph1bf + Bsz * Edim, pwp, out, MROWS, Vdim, Edim,
                              nullptr, nullptr, 1);

    // 7. post-processing
    postprocess<<<MROWS, 256>>>(out);
}

// round 17
// speedup vs baseline: 1.5028x; 1.0022x over previous
#include <cuda_runtime.h>
#include <cuda_bf16.h>
#include <math.h>
#include <stdint.h>

#define Bsz  4
#define Tlen 512
#define Edim 1024
#define Vdim 32000
#define GDIM (4*Edim)           // 4096
#define MROWS (Tlen*Bsz)        // 2048
#define NBLK 128
#define LOGB (-1.0005003335835335e-3)
#define FP8_SCALE   256.0f
#define FP8_UNSCALE (1.0f/65536.0f)

// ---------------- scratch ----------------
static __device__ __align__(16) __nv_bfloat16 g_xbf [MROWS * Edim];
static __device__ __align__(16) float g_gates[MROWS * GDIM];
static __device__ __align__(16) __nv_bfloat16 g_h0bf[(Tlen+1) * Bsz*Edim];
static __device__ __align__(16) __nv_bfloat16 g_h1bf[(Tlen+1) * Bsz*Edim];
static __device__ __align__(16) __nv_bfloat16 g_wih0bf[GDIM * Edim];
static __device__ __align__(16) __nv_bfloat16 g_wih1bf[GDIM * Edim];
static __device__ __align__(16) uint8_t g_wprojf8[(size_t)Vdim * Edim];
static __device__ __align__(16) uint8_t g_h1f8[MROWS * Edim];

// grid-barrier (proven)
static __device__ unsigned int g_arrive;
static __device__ unsigned int g_release;
__global__ void bar_reset() { g_arrive = 0; g_release = 0; }

// ---------------- helpers ----------------
__device__ __forceinline__ float tanh_acc(float x) {
    float ax = fabsf(x);
    float t  = expf(-2.f * ax);
    float r  = (1.f - t) / (1.f + t);
    return copysignf(r, x);
}
__device__ __forceinline__ float sigm(float x) { return 1.f / (1.f + expf(-x)); }

__device__ __forceinline__ void grid_barrier_t0(unsigned int gen) {
    __threadfence();
    unsigned int prev = atomicAdd(&g_arrive, 1u);
    if (prev + 1u == gen * NBLK) {
        __threadfence();
        asm volatile("st.release.gpu.u32 [%0], %1;"
                     :: "l"(&g_release), "r"(gen) : "memory");
    } else {
        unsigned int v;
        do {
            asm volatile("ld.acquire.gpu.u32 %0, [%1];"
                         : "=r"(v) : "l"(&g_release) : "memory");
        } while (v < gen);
    }
}

__device__ __forceinline__ void fma2(unsigned long long& acc,
                                     unsigned long long a, unsigned long long b) {
    asm("fma.rn.f32x2 %0, %1, %2, %0;" : "+l"(acc) : "l"(a), "l"(b));
}
__device__ __forceinline__ float f2sum(unsigned long long acc) {
    uint32_t lo, hi;
    asm("mov.b64 {%0,%1}, %2;" : "=r"(lo), "=r"(hi) : "l"(acc));
    return __uint_as_float(lo) + __uint_as_float(hi);
}
__device__ __forceinline__ unsigned long long packf2(float a, float b) {
    unsigned long long r;
    asm("mov.b64 %0, {%1,%2};" : "=l"(r) : "f"(a), "f"(b));
    return r;
}
__device__ __forceinline__ uint32_t packbf(float a, float b) {
    __nv_bfloat162 t = __floats2bfloat162_rn(a, b);
    return *(uint32_t*)&t;
}
__device__ __forceinline__ uint16_t packe4m3(float lo, float hi) {
    uint16_t r;
    asm("cvt.rn.satfinite.e4m3x2.f32 %0, %1, %2;" : "=h"(r) : "f"(hi), "f"(lo));
    return r;
}

__device__ __forceinline__ void ldsm_x4(uint32_t& r0, uint32_t& r1, uint32_t& r2, uint32_t& r3,
                                        uint32_t addr) {
    asm volatile("ldmatrix.sync.aligned.m8n8.x4.shared.b16 {%0,%1,%2,%3}, [%4];"
                 : "=r"(r0), "=r"(r1), "=r"(r2), "=r"(r3) : "r"(addr));
}
__device__ __forceinline__ void mma_bf16(float c[4], const uint32_t a[4], const uint32_t b[2]) {
    asm volatile(
        "mma.sync.aligned.m16n8k16.row.col.f32.bf16.bf16.f32 "
        "{%0,%1,%2,%3}, {%4,%5,%6,%7}, {%8,%9}, {%0,%1,%2,%3};"
        : "+f"(c[0]), "+f"(c[1]), "+f"(c[2]), "+f"(c[3])
        : "r"(a[0]), "r"(a[1]), "r"(a[2]), "r"(a[3]), "r"(b[0]), "r"(b[1]));
}
__device__ __forceinline__ void mma_fp8(float c[4], const uint32_t a[4], const uint32_t b[2]) {
    asm volatile(
        "mma.sync.aligned.m16n8k32.row.col.f32.e4m3.e4m3.f32 "
        "{%0,%1,%2,%3}, {%4,%5,%6,%7}, {%8,%9}, {%0,%1,%2,%3};"
        : "+f"(c[0]), "+f"(c[1]), "+f"(c[2]), "+f"(c[3])
        : "r"(a[0]), "r"(a[1]), "r"(a[2]), "r"(a[3]), "r"(b[0]), "r"(b[1]));
}

__device__ __forceinline__ void cp_async16(uint32_t dst, const void* src) {
    asm volatile("cp.async.ca.shared.global [%0], [%1], 16;"
                 :: "r"(dst), "l"(src) : "memory");
}
__device__ __forceinline__ void cp_commit() {
    asm volatile("cp.async.commit_group;" ::: "memory");
}
__device__ __forceinline__ void cp_wait0() {
    asm volatile("cp.async.wait_group 0;" ::: "memory");
}

// ---------------- conversions ----------------
__global__ void f2bf_kernel(const float* __restrict__ s, __nv_bfloat16* __restrict__ d, int n) {
    int idx = (blockIdx.x * blockDim.x + threadIdx.x) * 4;
    if (idx >= n) return;
    float4 v = *(const float4*)(s + idx);
    uint2 p;
    p.x = packbf(v.x, v.y); p.y = packbf(v.z, v.w);
    *(uint2*)(d + idx) = p;
}
// fp32 -> e4m3 (x FP8_SCALE), 8 elems/thread
__global__ void f2fp8_kernel(const float* __restrict__ s, uint8_t* __restrict__ d, int n) {
    int idx = (blockIdx.x * blockDim.x + threadIdx.x) * 8;
    if (idx >= n) return;
    float4 v0 = *(const float4*)(s + idx);
    float4 v1 = *(const float4*)(s + idx + 4);
    uint16_t h0 = packe4m3(v0.x * FP8_SCALE, v0.y * FP8_SCALE);
    uint16_t h1 = packe4m3(v0.z * FP8_SCALE, v0.w * FP8_SCALE);
    uint16_t h2 = packe4m3(v1.x * FP8_SCALE, v1.y * FP8_SCALE);
    uint16_t h3 = packe4m3(v1.z * FP8_SCALE, v1.w * FP8_SCALE);
    uint2 p;
    p.x = (uint32_t)h0 | ((uint32_t)h1 << 16);
    p.y = (uint32_t)h2 | ((uint32_t)h3 << 16);
    *(uint2*)(d + idx) = p;
}
// bf16 -> e4m3 (x FP8_SCALE), 8 elems/thread
__global__ void bf2fp8_kernel(const __nv_bfloat16* __restrict__ s, uint8_t* __restrict__ d, int n) {
    int idx = (blockIdx.x * blockDim.x + threadIdx.x) * 8;
    if (idx >= n) return;
    uint4 p = *(const uint4*)(s + idx);
    float f[8];
    f[0] = __uint_as_float(p.x << 16);  f[1] = __uint_as_float(p.x & 0xFFFF0000u);
    f[2] = __uint_as_float(p.y << 16);  f[3] = __uint_as_float(p.y & 0xFFFF0000u);
    f[4] = __uint_as_float(p.z << 16);  f[5] = __uint_as_float(p.z & 0xFFFF0000u);
    f[6] = __uint_as_float(p.w << 16);  f[7] = __uint_as_float(p.w & 0xFFFF0000u);
    uint16_t h0 = packe4m3(f[0] * FP8_SCALE, f[1] * FP8_SCALE);
    uint16_t h1 = packe4m3(f[2] * FP8_SCALE, f[3] * FP8_SCALE);
    uint16_t h2 = packe4m3(f[4] * FP8_SCALE, f[5] * FP8_SCALE);
    uint16_t h3 = packe4m3(f[6] * FP8_SCALE, f[7] * FP8_SCALE);
    uint2 q;
    q.x = (uint32_t)h0 | ((uint32_t)h1 << 16);
    q.y = (uint32_t)h2 | ((uint32_t)h3 << 16);
    *(uint2*)(d + idx) = q;
}

// ---------------- embedding ----------------
__global__ void embed_kernel(const int* __restrict__ tokens, const float* __restrict__ emb) {
    int id = blockIdx.x * blockDim.x + threadIdx.x;
    const int EV = Edim / 4;
    if (id >= MROWS * EV) return;
    int e4 = id % EV;
    int m  = id / EV;
    int b  = m & 3, t = m >> 2;
    int tok = tokens[b * Tlen + t];
    float4 v = ((const float4*)(emb + (size_t)tok * Edim))[e4];
    uint2 p; p.x = packbf(v.x, v.y); p.y = packbf(v.z, v.w);
    *(uint2*)(g_xbf + (size_t)id * 4) = p;
}

// ---------------- bf16 tensor-core GEMM (NT), cp.async double-buffered (gates) ----------------
__global__ __launch_bounds__(256)
void gemm_bf16_nt(const __nv_bfloat16* __restrict__ A, const __nv_bfloat16* __restrict__ B,
                  float* __restrict__ C, int M, int N, int K,
                  const float* __restrict__ bias1, const float* __restrict__ bias2,
                  int remap)
{
    __shared__ __align__(16) __nv_bfloat16 As[2][128 * 40];
    __shared__ __align__(16) __nv_bfloat16 Bs[2][128 * 40];
    const int tid  = threadIdx.x;
    const int wid  = tid >> 5, lane = tid & 31;
    const int g    = lane >> 2, tig = lane & 3;
    const int q    = lane >> 3, r = lane & 7;
    const int warp_m = (wid >> 2) * 64;
    const int warp_n = (wid & 3) * 32;
    const int row0 = blockIdx.x * 128;
    const int col0 = blockIdx.y * 128;

    const int ldr = tid >> 2;
    const int ldc = (tid & 3) * 8;

    const __nv_bfloat16* Ap0 = A + (size_t)(row0 + ldr) * K + ldc;
    const __nv_bfloat16* Ap1 = A + (size_t)(row0 + ldr + 64) * K + ldc;
    const __nv_bfloat16* Bp0 = B + (size_t)(col0 + ldr) * K + ldc;
    const __nv_bfloat16* Bp1 = B + (size_t)(col0 + ldr + 64) * K + ldc;

    uint32_t sa[2], sb[2];
    sa[0] = (uint32_t)__cvta_generic_to_shared(As[0]);
    sa[1] = (uint32_t)__cvta_generic_to_shared(As[1]);
    sb[0] = (uint32_t)__cvta_generic_to_shared(Bs[0]);
    sb[1] = (uint32_t)__cvta_generic_to_shared(Bs[1]);
    const uint32_t st_off0 = (uint32_t)((ldr * 40 + ldc) * 2);
    const uint32_t st_off1 = (uint32_t)(((ldr + 64) * 40 + ldc) * 2);
    const uint32_t frag_a  = (uint32_t)(((warp_m + (q & 1) * 8 + r) * 40 + (q >> 1) * 8) * 2);
    const uint32_t frag_b  = (uint32_t)(((warp_n + (q & 1) * 8 + r) * 40 + (q >> 1) * 8) * 2);

    float acc[16][4];
#pragma unroll
    for (int i = 0; i < 16; i++)
#pragma unroll
        for (int j = 0; j < 4; j++) acc[i][j] = 0.f;

    const int nslab = K / 32;

    cp_async16(sa[0] + st_off0, Ap0);
    cp_async16(sa[0] + st_off1, Ap1);
    cp_async16(sb[0] + st_off0, Bp0);
    cp_async16(sb[0] + st_off1, Bp1);
    cp_commit();

    for (int s = 0; s < nslab; s++) {
        const int bq = s & 1;
        cp_wait0();
        __syncthreads();

        if (s + 1 < nslab) {
            int off = (s + 1) * 32;
            cp_async16(sa[bq ^ 1] + st_off0, Ap0 + off);
            cp_async16(sa[bq ^ 1] + st_off1, Ap1 + off);
            cp_async16(sb[bq ^ 1] + st_off0, Bp0 + off);
            cp_async16(sb[bq ^ 1] + st_off1, Bp1 + off);
            cp_commit();
        }

        const uint32_t a_addr0 = sa[bq] + frag_a;
        const uint32_t b_addr0 = sb[bq] + frag_b;
#pragma unroll
        for (int ks = 0; ks < 2; ks++) {
            uint32_t af[4][4], bf[4][2];
#pragma unroll
            for (int mt = 0; mt < 4; mt++)
                ldsm_x4(af[mt][0], af[mt][1], af[mt][2], af[mt][3],
                        a_addr0 + (uint32_t)((mt * 16 * 40 + ks * 16) * 2));
#pragma unroll
            for (int bt = 0; bt < 2; bt++) {
                uint32_t m0, m1, m2, m3;
                ldsm_x4(m0, m1, m2, m3,
                        b_addr0 + (uint32_t)((bt * 16 * 40 + ks * 16) * 2));
                bf[bt * 2 + 0][0] = m0; bf[bt * 2 + 1][0] = m1;
                bf[bt * 2 + 0][1] = m2; bf[bt * 2 + 1][1] = m3;
            }
#pragma unroll
            for (int mt = 0; mt < 4; mt++)
#pragma unroll
                for (int nt = 0; nt < 4; nt++)
                    mma_bf16(acc[mt * 4 + nt], af[mt], bf[nt]);
        }
    }

#pragma unroll
    for (int mt = 0; mt < 4; mt++) {
        int m0 = row0 + warp_m + mt * 16 + g;
        int m1 = m0 + 8;
        int r0 = remap ? ((m0 & 3) * Tlen + (m0 >> 2)) : m0;
        int r1 = remap ? ((m1 & 3) * Tlen + (m1 >> 2)) : m1;
#pragma unroll
        for (int nt = 0; nt < 4; nt++) {
            int n = col0 + warp_n + nt * 8 + tig * 2;
            float bv0 = 0.f, bv1 = 0.f;
            if (bias1) { bv0 += bias1[n]; bv1 += bias1[n + 1]; }
            if (bias2) { bv0 += bias2[n]; bv1 += bias2[n + 1]; }
            float* c = acc[mt * 4 + nt];
            *(float2*)&C[(size_t)r0 * N + n] = make_float2(c[0] + bv0, c[1] + bv1);
            *(float2*)&C[(size_t)r1 * N + n] = make_float2(c[2] + bv0, c[3] + bv1);
        }
    }
}

// ---------------- fp8 e4m3 GEMM (NT), cp.async double-buffered (projection) ----------------
// A,B scaled by FP8_SCALE; epilogue multiplies by FP8_UNSCALE. Rows remapped [B,T].
// SMEM rows: 64 fp8 of K per slab, stride 80 B (banks 0,20,8,28,16,4,24,12 — conflict-free).
__global__ __launch_bounds__(256)
void gemm_fp8_nt(const uint8_t* __restrict__ A, const uint8_t* __restrict__ B,
                 float* __restrict__ C, int M, int N, int K)
{
    __shared__ __align__(16) uint8_t As[2][128 * 80];
    __shared__ __align__(16) uint8_t Bs[2][128 * 80];
    const int tid  = threadIdx.x;
    const int wid  = tid >> 5, lane = tid & 31;
    const int g    = lane >> 2, tig = lane & 3;
    const int q    = lane >> 3, r = lane & 7;
    const int warp_m = (wid >> 2) * 64;
    const int warp_n = (wid & 3) * 32;
    const int row0 = blockIdx.x * 128;
    const int col0 = blockIdx.y * 128;

    const int ldr = tid >> 2;           // 0..63
    const int ldc = (tid & 3) * 16;     // byte 0,16,32,48 (covers 64B of K)

    const uint8_t* Ap0 = A + (size_t)(row0 + ldr) * K + ldc;
    const uint8_t* Ap1 = A + (size_t)(row0 + ldr + 64) * K + ldc;
    const uint8_t* Bp0 = B + (size_t)(col0 + ldr) * K + ldc;
    const uint8_t* Bp1 = B + (size_t)(col0 + ldr + 64) * K + ldc;

    uint32_t sa[2], sb[2];
    sa[0] = (uint32_t)__cvta_generic_to_shared(As[0]);
    sa[1] = (uint32_t)__cvta_generic_to_shared(As[1]);
    sb[0] = (uint32_t)__cvta_generic_to_shared(Bs[0]);
    sb[1] = (uint32_t)__cvta_generic_to_shared(Bs[1]);
    const uint32_t st_off0 = (uint32_t)(ldr * 80 + ldc);
    const uint32_t st_off1 = (uint32_t)((ldr + 64) * 80 + ldc);
    // fragment base: row (warp_m + (q&1)*8 + r), k-half (q>>1)*16 bytes
    const uint32_t frag_a = (uint32_t)((warp_m + (q & 1) * 8 + r) * 80 + (q >> 1) * 16);
    const uint32_t frag_b = (uint32_t)((warp_n + (q & 1) * 8 + r) * 80 + (q >> 1) * 16);

    float acc[16][4];
#pragma unroll
    for (int i = 0; i < 16; i++)
#pragma unroll
        for (int j = 0; j < 4; j++) acc[i][j] = 0.f;

    const int nslab = K / 64;           // 16 slabs of 64 fp8

    cp_async16(sa[0] + st_off0, Ap0);
    cp_async16(sa[0] + st_off1, Ap1);
    cp_async16(sb[0] + st_off0, Bp0);
    cp_async16(sb[0] + st_off1, Bp1);
    cp_commit();

    for (int s = 0; s < nslab; s++) {
        const int bq = s & 1;
        cp_wait0();
        __syncthreads();

        if (s + 1 < nslab) {
            int off = (s + 1) * 64;
            cp_async16(sa[bq ^ 1] + st_off0, Ap0 + off);
            cp_async16(sa[bq ^ 1] + st_off1, Ap1 + off);
            cp_async16(sb[bq ^ 1] + st_off0, Bp0 + off);
            cp_async16(sb[bq ^ 1] + st_off1, Bp1 + off);
            cp_commit();
        }

        const uint32_t a_addr0 = sa[bq] + frag_a;
        const uint32_t b_addr0 = sb[bq] + frag_b;
#pragma unroll
        for (int ks = 0; ks < 2; ks++) {          // two k32 steps per 64-fp8 slab
            uint32_t af[4][4], bf[4][2];
#pragma unroll
            for (int mt = 0; mt < 4; mt++)
                ldsm_x4(af[mt][0], af[mt][1], af[mt][2], af[mt][3],
                        a_addr0 + (uint32_t)(mt * 16 * 80 + ks * 32));
#pragma unroll
            for (int bt = 0; bt < 2; bt++) {
                uint32_t m0, m1, m2, m3;
                ldsm_x4(m0, m1, m2, m3,
                        b_addr0 + (uint32_t)(bt * 16 * 80 + ks * 32));
                bf[bt * 2 + 0][0] = m0; bf[bt * 2 + 1][0] = m1;
                bf[bt * 2 + 0][1] = m2; bf[bt * 2 + 1][1] = m3;
            }
#pragma unroll
            for (int mt = 0; mt < 4; mt++)
#pragma unroll
                for (int nt = 0; nt < 4; nt++)
                    mma_fp8(acc[mt * 4 + nt], af[mt], bf[nt]);
        }
    }

#pragma unroll
    for (int mt = 0; mt < 4; mt++) {
        int m0 = row0 + warp_m + mt * 16 + g;
        int m1 = m0 + 8;
        int r0 = (m0 & 3) * Tlen + (m0 >> 2);
        int r1 = (m1 & 3) * Tlen + (m1 >> 2);
#pragma unroll
        for (int nt = 0; nt < 4; nt++) {
            int n = col0 + warp_n + nt * 8 + tig * 2;
            float* c = acc[mt * 4 + nt];
            *(float2*)&C[(size_t)r0 * N + n] =
                make_float2(c[0] * FP8_UNSCALE, c[1] * FP8_UNSCALE);
            *(float2*)&C[(size_t)r1 * N + n] =
                make_float2(c[2] * FP8_UNSCALE, c[3] * FP8_UNSCALE);
        }
    }
}

// ---------------- persistent LSTM layer (round-16 proven) ----------------
__global__ void __launch_bounds__(256, 1)
lstm_layer(const float* __restrict__ gih,
           const float* __restrict__ Whh,
           __nv_bfloat16* __restrict__ hbf,
           unsigned int gen_base)
{
    __shared__ __align__(16) float hs[4 * Edim];
    __shared__ float garr[128];
    __shared__ float cs[32];

    const int blk  = blockIdx.x;
    const int e0   = blk * 8;
    const int tid  = threadIdx.x;
    const int warp = tid >> 5;
    const int lane = tid & 31;

    unsigned long long wreg[4][16];
#pragma unroll
    for (int rr = 0; rr < 4; rr++) {
        int r = warp * 4 + rr, g = r >> 3, j = r & 7;
        const float* src = Whh + (size_t)(g * Edim + e0 + j) * Edim;
#pragma unroll
        for (int jj = 0; jj < 16; jj++) {
            int kp = lane + 32 * jj;
            float2 v = *(const float2*)&src[kp * 2];
            wreg[rr][jj] = packf2(v.x, v.y);
        }
    }
    if (tid < 32) cs[tid] = 0.f;
    __syncthreads();

    const int pb = tid >> 3, pj = tid & 7, pe = e0 + pj;

    for (int t = 0; t < Tlen; t++) {
        float pgi = 0.f, pgf = 0.f, pgG = 0.f, pgo = 0.f;
        if (tid < 32) {
            const float* gb = gih + ((size_t)t * Bsz + pb) * GDIM;
            pgi = __ldg(&gb[pe]);
            pgf = __ldg(&gb[Edim + pe]);
            pgG = __ldg(&gb[2 * Edim + pe]);
            pgo = __ldg(&gb[3 * Edim + pe]);
        }

        if (t == 0) {
            for (int i = tid; i < 4 * Edim; i += 256) hs[i] = 0.f;
        } else {
            const uint4* hp = (const uint4*)(hbf + (size_t)t * (Bsz * Edim));
#pragma unroll
            for (int i = tid; i < 512; i += 256) {
                uint4 p = hp[i];
                float* d = hs + i * 8;
                d[0] = __uint_as_float(p.x << 16);
                d[1] = __uint_as_float(p.x & 0xFFFF0000u);
                d[2] = __uint_as_float(p.y << 16);
                d[3] = __uint_as_float(p.y & 0xFFFF0000u);
                d[4] = __uint_as_float(p.z << 16);
                d[5] = __uint_as_float(p.z & 0xFFFF0000u);
                d[6] = __uint_as_float(p.w << 16);
                d[7] = __uint_as_float(p.w & 0xFFFF0000u);
            }
        }
        __syncthreads();

        unsigned long long acc[16];
#pragma unroll
        for (int i = 0; i < 16; i++) acc[i] = 0ull;

#pragma unroll
        for (int jj = 0; jj < 16; jj++) {
            int kp = lane + 32 * jj;
            unsigned long long H0 = *(const unsigned long long*)&hs[kp * 2];
            unsigned long long H1 = *(const unsigned long long*)&hs[Edim + kp * 2];
            unsigned long long H2 = *(const unsigned long long*)&hs[2 * Edim + kp * 2];
            unsigned long long H3 = *(const unsigned long long*)&hs[3 * Edim + kp * 2];
            fma2(acc[ 0], wreg[0][jj], H0); fma2(acc[ 1], wreg[0][jj], H1);
            fma2(acc[ 2], wreg[0][jj], H2); fma2(acc[ 3], wreg[0][jj], H3);
            fma2(acc[ 4], wreg[1][jj], H0); fma2(acc[ 5], wreg[1][jj], H1);
            fma2(acc[ 6], wreg[1][jj], H2); fma2(acc[ 7], wreg[1][jj], H3);
            fma2(acc[ 8], wreg[2][jj], H0); fma2(acc[ 9], wreg[2][jj], H1);
            fma2(acc[10], wreg[2][jj], H2); fma2(acc[11], wreg[2][jj], H3);
            fma2(acc[12], wreg[3][jj], H0); fma2(acc[13], wreg[3][jj], H1);
            fma2(acc[14], wreg[3][jj], H2); fma2(acc[15], wreg[3][jj], H3);
        }

        float a[16];
#pragma unroll
        for (int i = 0; i < 16; i++) a[i] = f2sum(acc[i]);
#pragma unroll
        for (int off = 16; off; off >>= 1)
#pragma unroll
            for (int i = 0; i < 16; i++)
                a[i] += __shfl_down_sync(~0u, a[i], off);

        if (lane == 0) {
#pragma unroll
            for (int rr = 0; rr < 4; rr++) {
                int r = warp * 4 + rr, g = r >> 3, j = r & 7;
#pragma unroll
                for (int b = 0; b < 4; b++)
                    garr[(g * 4 + b) * 8 + j] = a[rr * 4 + b];
            }
        }
        __syncthreads();

        if (tid < 32) {
            float gi = garr[(0 * 4 + pb) * 8 + pj] + pgi;
            float gf = garr[(1 * 4 + pb) * 8 + pj] + pgf;
            float gG = garr[(2 * 4 + pb) * 8 + pj] + pgG;
            float go = garr[(3 * 4 + pb) * 8 + pj] + pgo;
            float c = sigm(gf) * cs[tid] + sigm(gi) * tanh_acc(gG);
            cs[tid] = c;
            float hv = sigm(go) * tanh_acc(c);
            hbf[(size_t)(t + 1) * (Bsz * Edim) + pb * Edim + pe] = __float2bfloat16(hv);
            __syncwarp();
            if (tid == 0) grid_barrier_t0(gen_base + (unsigned int)(t + 1));
        }
        __syncthreads();
    }
}

// ---------------- post-processing (proven) ----------------
__global__ void postprocess(float* __restrict__ out) {
    const int r = blockIdx.x;
    const int t_idx = r & (Tlen - 1);
    float* z = out + (size_t)r * Vdim;
    const int tid = threadIdx.x;

    __shared__ float redm[256];
    __shared__ float reds[256];
    __shared__ float sh_shift, sh_eos;

    float m = -3.402823466e38f, s = 0.f;
    const float4* z4 = (const float4*)z;
    for (int i = tid; i < 7999; i += 256) {
        float4 v = z4[i];
        float mv = fmaxf(fmaxf(v.x, v.y), fmaxf(v.z, v.w));
        float m2 = fmaxf(m, mv);
        s = s * expf(m - m2)
          + expf(v.x - m2) + expf(v.y - m2) + expf(v.z - m2) + expf(v.w - m2);
        m = m2;
    }
    if (tid < 3) {
        float x = z[31996 + tid];
        float m2 = fmaxf(m, x);
        s = s * expf(m - m2) + expf(x - m2);
        m = m2;
    }
    redm[tid] = m; reds[tid] = s;
    __syncthreads();
#pragma unroll
    for (int st = 128; st; st >>= 1) {
        if (tid < st) {
            float mo = redm[tid], so = reds[tid];
            float mn = redm[tid + st], sn = reds[tid + st];
            float mm = fmaxf(mo, mn);
            redm[tid] = mm;
            reds[tid] = so * expf(mo - mm) + sn * expf(mn - mm);
        }
        __syncthreads();
    }

    if (tid == 0) {
        double lse = (double)redm[0] + log((double)reds[0]);
        double e   = (double)z[Vdim - 1];
        double lsn = (-e < 0 ? -e : 0.0) - log1p(exp(-fabs(e)));
        double lsp = ( e < 0 ?  e : 0.0) - log1p(exp(-fabs(e)));
        double log_lb = (double)(t_idx + 1) * LOGB;
        double C1 = log_lb + lsn;
        double log_lb_eos = log(-expm1(log_lb)) + lsn;
        double d = log_lb_eos - lsp;
        double logsig_d = (d < 0 ? d : 0.0) - log1p(exp(-fabs(d)));
        double lpe = log_lb_eos - logsig_d;
        double m2 = fmax(C1, lpe);
        double Z  = m2 + log1p(exp(fmin(C1, lpe) - m2));
        sh_shift = (float)(C1 - lse - Z);
        sh_eos   = (float)(lpe - Z);
    }
    __syncthreads();

    float shift = sh_shift;
    float4* zw = (float4*)z;
    for (int i = tid; i < 7999; i += 256) {
        float4 v = zw[i];
        v.x += shift; v.y += shift; v.z += shift; v.w += shift;
        zw[i] = v;
    }
    if (tid < 3) z[31996 + tid] += shift;
    if (tid == 0) z[Vdim - 1] = sh_eos;
}

// ---------------- launcher ----------------
extern "C" void kernel_launch(void* const* d_in, const int* in_sizes, int n_in,
                              void* d_out, int out_size)
{
    (void)in_sizes; (void)n_in; (void)out_size;
    // 0:tokens 1:emb 2:Wproj 3:Wih0 4:Whh0 5:bih0 6:bhh0 7:Wih1 8:Whh1 9:bih1 10:bhh1
    const int*   tokens = (const int*)  d_in[0];
    const float* emb    = (const float*)d_in[1];
    const float* Wproj  = (const float*)d_in[2];
    const float* Wih0   = (const float*)d_in[3];
    const float* Whh0   = (const float*)d_in[4];
    const float* bih0   = (const float*)d_in[5];
    const float* bhh0   = (const float*)d_in[6];
    const float* Wih1   = (const float*)d_in[7];
    const float* Whh1   = (const float*)d_in[8];
    const float* bih1   = (const float*)d_in[9];
    const float* bhh1   = (const float*)d_in[10];
    float* out = (float*)d_out;

    __nv_bfloat16 *pxbf, *ph0bf, *ph1bf, *pw0, *pw1;
    uint8_t *pwp8, *ph1f8;
    float *pg;
    cudaGetSymbolAddress((void**)&pxbf,  g_xbf);
    cudaGetSymbolAddress((void**)&pg,    g_gates);
    cudaGetSymbolAddress((void**)&ph0bf, g_h0bf);
    cudaGetSymbolAddress((void**)&ph1bf, g_h1bf);
    cudaGetSymbolAddress((void**)&pw0,   g_wih0bf);
    cudaGetSymbolAddress((void**)&pw1,   g_wih1bf);
    cudaGetSymbolAddress((void**)&pwp8,  g_wprojf8);
    cudaGetSymbolAddress((void**)&ph1f8, g_h1f8);

    // 0. barrier reset + weight conversions
    bar_reset<<<1, 1>>>();
    f2bf_kernel<<<GDIM * Edim / 1024, 256>>>(Wih0, pw0, GDIM * Edim);
    f2bf_kernel<<<GDIM * Edim / 1024, 256>>>(Wih1, pw1, GDIM * Edim);
    f2fp8_kernel<<<Vdim * Edim / 2048, 256>>>(Wproj, pwp8, Vdim * Edim);

    // 1. embedding
    embed_kernel<<<(MROWS * Edim / 4 + 255) / 256, 256>>>(tokens, emb);

    // 2. layer-0 input gates
    dim3 gg(MROWS / 128, GDIM / 128);
    gemm_bf16_nt<<<gg, 256>>>(pxbf, pw0, pg, MROWS, GDIM, Edim, bih0, bhh0, 0);

    // 3. layer-0 recurrence (generations 1..512)
    lstm_layer<<<NBLK, 256>>>(pg, Whh0, ph0bf, 0u);

    // 4. layer-1 input gates
    gemm_bf16_nt<<<gg, 256>>>(ph0bf + Bsz * Edim, pw1, pg, MROWS, GDIM, Edim, bih1, bhh1, 0);

    // 5. layer-1 recurrence (generations 513..1024)
    lstm_layer<<<NBLK, 256>>>(pg, Whh1, ph1bf, (unsigned int)Tlen);

    // 5b. h1 -> fp8 (scaled)
    bf2fp8_kernel<<<MROWS * Edim / 2048, 256>>>(ph1bf + Bsz * Edim, ph1f8, MROWS * Edim);

    // 6. projection (fp8 e4m3 QMMA) -> d_out with [B,T] remap
    dim3 gp(MROWS / 128, Vdim / 128);
    gemm_fp8_nt<<<gp, 256>>>(ph1f8, pwp8, out, MROWS, Vdim, Edim);

    // 7. post-processing
    postprocess<<<MROWS, 256>>>(out);
}